// round 1
// baseline (speedup 1.0000x reference)
#include <cuda_runtime.h>
#include <math.h>

// Problem constants (fixed shapes for this dataset)
#define NN 50000
#define EE 800000
#define BB 128
#define IN_DIM 310
#define HD 128      // 2 heads x 64
#define NH 2

// ---------------- scratch (static device globals; no allocation) ----------------
__device__ float g_xw[NN * HD];      // GEMM output (xw of current layer)
__device__ float g_h[NN * HD];       // aggregated layer output
__device__ float g_asrc[NN * NH];
__device__ float g_adst[NN * NH];
__device__ int   g_deg[NN];
__device__ int   g_cursor[NN];
__device__ int   g_rowptr[NN + 1];
__device__ int   g_csrsrc[EE];
__device__ int   g_root[BB + 1];

__device__ __forceinline__ float lrelu(float z) { return z > 0.f ? z : 0.2f * z; }

// ---------------- CSR build ----------------
__global__ void zero_kernel() {
    int i = blockIdx.x * blockDim.x + threadIdx.x;
    if (i < NN) { g_deg[i] = 0; g_cursor[i] = 0; }
}

__global__ void count_kernel(const int* __restrict__ dst) {
    int i = blockIdx.x * blockDim.x + threadIdx.x;
    if (i < EE) atomicAdd(&g_deg[dst[i]], 1);
}

__global__ void scan_kernel() {
    __shared__ int wsum[32];
    __shared__ int s_base;
    int t = threadIdx.x, lane = t & 31, wid = t >> 5;
    if (t == 0) s_base = 0;
    __syncthreads();
    for (int base = 0; base < NN; base += 1024) {
        int i = base + t;
        int v = (i < NN) ? g_deg[i] : 0;
        int x = v;
        #pragma unroll
        for (int o = 1; o < 32; o <<= 1) {
            int y = __shfl_up_sync(0xffffffffu, x, o);
            if (lane >= o) x += y;
        }
        if (lane == 31) wsum[wid] = x;
        __syncthreads();
        if (wid == 0) {
            int w = wsum[lane];
            #pragma unroll
            for (int o = 1; o < 32; o <<= 1) {
                int y = __shfl_up_sync(0xffffffffu, w, o);
                if (lane >= o) w += y;
            }
            wsum[lane] = w;
        }
        __syncthreads();
        int excl = x - v + (wid ? wsum[wid - 1] : 0);
        if (i < NN) g_rowptr[i] = s_base + excl;
        int total = wsum[31];
        __syncthreads();
        if (t == 0) s_base += total;
        __syncthreads();
    }
    if (t == 0) g_rowptr[NN] = s_base;
}

__global__ void fill_kernel(const int* __restrict__ src, const int* __restrict__ dst) {
    int i = blockIdx.x * blockDim.x + threadIdx.x;
    if (i < EE) {
        int d = dst[i];
        int pos = g_rowptr[d] + atomicAdd(&g_cursor[d], 1);
        g_csrsrc[pos] = src[i];
    }
}

__global__ void roots_kernel(const int* __restrict__ batch) {
    int b = threadIdx.x;
    if (b > BB) return;
    if (b == BB) { g_root[BB] = NN; return; }
    int lo = 0, hi = NN;  // first idx with batch[idx] >= b
    while (lo < hi) {
        int mid = (lo + hi) >> 1;
        if (batch[mid] < b) lo = mid + 1; else hi = mid;
    }
    g_root[b] = lo;
}

// ---------------- GEMM: C[M,128] = A[M,K] @ B[K,128] ----------------
__global__ void gemm128(const float* __restrict__ A, const float* __restrict__ Bm,
                        float* __restrict__ C, int M, int K) {
    __shared__ float As[16][129];
    __shared__ float Bs[16][128];
    int tid = threadIdx.x;            // 256
    int tr = tid >> 4, tc = tid & 15;
    int row0 = blockIdx.x * 128;
    float acc[8][8];
    #pragma unroll
    for (int i = 0; i < 8; i++)
        #pragma unroll
        for (int j = 0; j < 8; j++) acc[i][j] = 0.f;

    for (int k0 = 0; k0 < K; k0 += 16) {
        #pragma unroll
        for (int t = 0; t < 8; t++) {
            int id = tid + t * 256;
            int m = id >> 4, kk = id & 15;
            int gm = row0 + m, gk = k0 + kk;
            As[kk][m] = (gm < M && gk < K) ? A[(long)gm * K + gk] : 0.f;
        }
        #pragma unroll
        for (int t = 0; t < 8; t++) {
            int id = tid + t * 256;
            int kk = id >> 7, n = id & 127;
            int gk = k0 + kk;
            Bs[kk][n] = (gk < K) ? Bm[gk * 128 + n] : 0.f;
        }
        __syncthreads();
        #pragma unroll
        for (int kk = 0; kk < 16; kk++) {
            float a[8], b[8];
            #pragma unroll
            for (int i = 0; i < 8; i++) a[i] = As[kk][tr * 8 + i];
            float4 b0 = *reinterpret_cast<const float4*>(&Bs[kk][tc * 8]);
            float4 b1 = *reinterpret_cast<const float4*>(&Bs[kk][tc * 8 + 4]);
            b[0] = b0.x; b[1] = b0.y; b[2] = b0.z; b[3] = b0.w;
            b[4] = b1.x; b[5] = b1.y; b[6] = b1.z; b[7] = b1.w;
            #pragma unroll
            for (int i = 0; i < 8; i++)
                #pragma unroll
                for (int j = 0; j < 8; j++)
                    acc[i][j] = fmaf(a[i], b[j], acc[i][j]);
        }
        __syncthreads();
    }
    #pragma unroll
    for (int i = 0; i < 8; i++) {
        int gm = row0 + tr * 8 + i;
        if (gm < M) {
            #pragma unroll
            for (int j = 0; j < 8; j += 4) {
                float4 v = make_float4(acc[i][j], acc[i][j + 1], acc[i][j + 2], acc[i][j + 3]);
                *reinterpret_cast<float4*>(&C[gm * 128 + tc * 8 + j]) = v;
            }
        }
    }
}

// ---------------- per-node attention logits: alpha_src/dst = sum(xw * a) ----------------
__global__ void alpha_kernel(const float* __restrict__ xw,
                             const float* __restrict__ a_src,
                             const float* __restrict__ a_dst) {
    int gw = (blockIdx.x * blockDim.x + threadIdx.x) >> 5;
    int lane = threadIdx.x & 31;
    if (gw >= NN) return;
    float4 v = *reinterpret_cast<const float4*>(&xw[gw * HD + lane * 4]);
    int head = lane >> 4;
    int ci = (lane * 4) & 63;
    float4 s4 = *reinterpret_cast<const float4*>(&a_src[head * 64 + ci]);
    float4 d4 = *reinterpret_cast<const float4*>(&a_dst[head * 64 + ci]);
    float ss = v.x * s4.x + v.y * s4.y + v.z * s4.z + v.w * s4.w;
    float dd = v.x * d4.x + v.y * d4.y + v.z * d4.z + v.w * d4.w;
    #pragma unroll
    for (int o = 8; o; o >>= 1) {
        ss += __shfl_down_sync(0xffffffffu, ss, o, 16);
        dd += __shfl_down_sync(0xffffffffu, dd, o, 16);
    }
    if ((lane & 15) == 0) {
        g_asrc[gw * 2 + head] = ss;
        g_adst[gw * 2 + head] = dd;
    }
}

// ---------------- GAT aggregation: warp per dst node, softmax + weighted sum ----------------
__global__ void aggregate_kernel(const float* __restrict__ xw,
                                 const float* __restrict__ bias,
                                 float* __restrict__ out) {
    int gw = (blockIdx.x * blockDim.x + threadIdx.x) >> 5;
    int lane = threadIdx.x & 31;
    if (gw >= NN) return;
    int i = gw;
    float ad0 = g_adst[2 * i], ad1 = g_adst[2 * i + 1];
    float es0 = lrelu(g_asrc[2 * i] + ad0);
    float es1 = lrelu(g_asrc[2 * i + 1] + ad1);
    int r0 = g_rowptr[i], r1 = g_rowptr[i + 1];

    // pass 1: max (self-loop included)
    float m0 = es0, m1 = es1;
    for (int j = r0 + lane; j < r1; j += 32) {
        int s = g_csrsrc[j];
        m0 = fmaxf(m0, lrelu(g_asrc[2 * s] + ad0));
        m1 = fmaxf(m1, lrelu(g_asrc[2 * s + 1] + ad1));
    }
    #pragma unroll
    for (int o = 16; o; o >>= 1) {
        m0 = fmaxf(m0, __shfl_xor_sync(0xffffffffu, m0, o));
        m1 = fmaxf(m1, __shfl_xor_sync(0xffffffffu, m1, o));
    }

    // pass 2: denominator
    float s0 = 0.f, s1 = 0.f;
    for (int j = r0 + lane; j < r1; j += 32) {
        int s = g_csrsrc[j];
        s0 += expf(lrelu(g_asrc[2 * s] + ad0) - m0);
        s1 += expf(lrelu(g_asrc[2 * s + 1] + ad1) - m1);
    }
    #pragma unroll
    for (int o = 16; o; o >>= 1) {
        s0 += __shfl_xor_sync(0xffffffffu, s0, o);
        s1 += __shfl_xor_sync(0xffffffffu, s1, o);
    }
    s0 += expf(es0 - m0);
    s1 += expf(es1 - m1);
    float inv0 = 1.f / (s0 + 1e-16f);
    float inv1 = 1.f / (s1 + 1e-16f);

    // pass 3: weighted message sum; lane covers cols [4*lane, 4*lane+4)
    int head = lane >> 4;
    float4 acc = make_float4(0.f, 0.f, 0.f, 0.f);
    for (int jb = r0; jb < r1; jb += 32) {
        int j = jb + lane;
        int s = 0; float w0 = 0.f, w1 = 0.f;
        if (j < r1) {
            s = g_csrsrc[j];
            w0 = expf(lrelu(g_asrc[2 * s] + ad0) - m0) * inv0;
            w1 = expf(lrelu(g_asrc[2 * s + 1] + ad1) - m1) * inv1;
        }
        int cnt = min(32, r1 - jb);
        for (int k = 0; k < cnt; k++) {
            int   sk  = __shfl_sync(0xffffffffu, s, k);
            float wk0 = __shfl_sync(0xffffffffu, w0, k);
            float wk1 = __shfl_sync(0xffffffffu, w1, k);
            float wk = head ? wk1 : wk0;
            float4 v = *reinterpret_cast<const float4*>(&xw[sk * HD + lane * 4]);
            acc.x = fmaf(wk, v.x, acc.x);
            acc.y = fmaf(wk, v.y, acc.y);
            acc.z = fmaf(wk, v.z, acc.z);
            acc.w = fmaf(wk, v.w, acc.w);
        }
    }
    float wself = head ? (expf(es1 - m1) * inv1) : (expf(es0 - m0) * inv0);
    float4 vs = *reinterpret_cast<const float4*>(&xw[i * HD + lane * 4]);
    acc.x = fmaf(wself, vs.x, acc.x);
    acc.y = fmaf(wself, vs.y, acc.y);
    acc.z = fmaf(wself, vs.z, acc.z);
    acc.w = fmaf(wself, vs.w, acc.w);

    float4 b = *reinterpret_cast<const float4*>(&bias[lane * 4]);
    float4 o;
    o.x = fmaxf(acc.x + b.x, 0.f);
    o.y = fmaxf(acc.y + b.y, 0.f);
    o.z = fmaxf(acc.z + b.z, 0.f);
    o.w = fmaxf(acc.w + b.w, 0.f);
    *reinterpret_cast<float4*>(&out[i * HD + lane * 4]) = o;
}

// ---------------- pool + readout + news + concat + sigmoid (block per graph) ----------------
__global__ void head_kernel(const float* __restrict__ h, const float* __restrict__ x,
                            const float* __restrict__ Wr, const float* __restrict__ br,
                            const float* __restrict__ Wn, const float* __restrict__ bn,
                            const float* __restrict__ Wc, const float* __restrict__ bc,
                            float* __restrict__ out) {
    int b = blockIdx.x;
    int t = threadIdx.x;   // 128
    __shared__ float pooled[128];
    __shared__ float xroot[312];
    __shared__ float red[128];

    int r0 = g_root[b], r1 = g_root[b + 1];
    float s = 0.f;
    for (int n = r0; n < r1; n++) s += h[n * 128 + t];
    pooled[t] = s / (float)(r1 - r0);
    for (int k = t; k < IN_DIM; k += 128) xroot[k] = x[(long)r0 * IN_DIM + k];
    __syncthreads();

    float accg = br[t];
    #pragma unroll 4
    for (int k = 0; k < 128; k++) accg = fmaf(pooled[k], Wr[k * 128 + t], accg);
    float g = fmaxf(accg, 0.f);

    float accn = bn[t];
    for (int k = 0; k < IN_DIM; k++) accn = fmaf(xroot[k], Wn[k * 128 + t], accn);
    float nws = fmaxf(accn, 0.f);

    red[t] = g * Wc[t] + nws * Wc[128 + t];
    __syncthreads();
    for (int o = 64; o; o >>= 1) {
        if (t < o) red[t] += red[t + o];
        __syncthreads();
    }
    if (t == 0) out[b] = 1.f / (1.f + expf(-(red[0] + bc[0])));
}

// ---------------- launch ----------------
extern "C" void kernel_launch(void* const* d_in, const int* in_sizes, int n_in,
                              void* d_out, int out_size) {
    const float* x   = (const float*)d_in[0];
    const float* W0  = (const float*)d_in[1];
    const float* as0 = (const float*)d_in[2];
    const float* ad0 = (const float*)d_in[3];
    const float* b0  = (const float*)d_in[4];
    const float* W1  = (const float*)d_in[5];
    const float* as1 = (const float*)d_in[6];
    const float* ad1 = (const float*)d_in[7];
    const float* b1  = (const float*)d_in[8];
    const float* Wn  = (const float*)d_in[9];
    const float* bn  = (const float*)d_in[10];
    const float* Wr  = (const float*)d_in[11];
    const float* br  = (const float*)d_in[12];
    const float* Wc  = (const float*)d_in[13];
    const float* bc  = (const float*)d_in[14];
    const int*   ei  = (const int*)d_in[15];
    const int*   batch = (const int*)d_in[16];
    float* out = (float*)d_out;

    const int* src = ei;
    const int* dst = ei + EE;

    void *p_xw = nullptr, *p_h = nullptr;
    cudaGetSymbolAddress(&p_xw, g_xw);
    cudaGetSymbolAddress(&p_h, g_h);
    float* xw = (float*)p_xw;
    float* hbuf = (float*)p_h;

    // CSR build (reused for both GAT layers)
    zero_kernel<<<(NN + 255) / 256, 256>>>();
    count_kernel<<<(EE + 255) / 256, 256>>>(dst);
    scan_kernel<<<1, 1024>>>();
    fill_kernel<<<(EE + 255) / 256, 256>>>(src, dst);
    roots_kernel<<<1, 256>>>(batch);

    // GAT layer 0
    gemm128<<<(NN + 127) / 128, 256>>>(x, W0, xw, NN, IN_DIM);
    alpha_kernel<<<(NN + 7) / 8, 256>>>(xw, as0, ad0);
    aggregate_kernel<<<(NN + 7) / 8, 256>>>(xw, b0, hbuf);

    // GAT layer 1
    gemm128<<<(NN + 127) / 128, 256>>>(hbuf, W1, xw, NN, HD);
    alpha_kernel<<<(NN + 7) / 8, 256>>>(xw, as1, ad1);
    aggregate_kernel<<<(NN + 7) / 8, 256>>>(xw, b1, hbuf);

    // pooling + readout + news + concat + sigmoid
    head_kernel<<<BB, 128>>>(hbuf, x, Wr, br, Wn, bn, Wc, bc, out);
}

// round 3
// speedup vs baseline: 1.5338x; 1.5338x over previous
#include <cuda_runtime.h>
#include <cuda_bf16.h>
#include <cuda_fp16.h>
#include <stdint.h>
#include <math.h>

// Problem constants (fixed shapes for this dataset)
#define NN 50000
#define EE 800000
#define BB 128
#define IN_DIM 310
#define KP0 320      // IN_DIM padded to multiple of 32
#define HD 128       // 2 heads x 64
#define NH 2

// ---------------- scratch (static device globals; no allocation) ----------------
__device__ __align__(16) float g_xw[NN * HD];        // GEMM output fp32 (for alpha)
__device__ __align__(16) __half g_xwh[NN * HD];      // GEMM output fp16 (for gather)
__device__ __align__(16) float g_h[NN * HD];         // aggregated layer output
__device__ float g_asrc[NN * NH];
__device__ float g_adst[NN * NH];
__device__ int   g_deg[NN];
__device__ int   g_cursor[NN];
__device__ int   g_rowptr[NN + 1];
__device__ int   g_csrsrc[EE];
__device__ int   g_root[BB + 1];
// pre-split weight matrices (bf16 hi/lo), zero-padded along K
__device__ __align__(16) __nv_bfloat16 g_Bhi0[KP0 * 128];
__device__ __align__(16) __nv_bfloat16 g_Blo0[KP0 * 128];
__device__ __align__(16) __nv_bfloat16 g_Bhi1[128 * 128];
__device__ __align__(16) __nv_bfloat16 g_Blo1[128 * 128];

__device__ __forceinline__ float lrelu(float z) { return z > 0.f ? z : 0.2f * z; }

// ---------------- CSR build ----------------
__global__ void zero_kernel() {
    int i = blockIdx.x * blockDim.x + threadIdx.x;
    if (i < NN) { g_deg[i] = 0; g_cursor[i] = 0; }
}

__global__ void count_kernel(const int* __restrict__ dst) {
    int i = blockIdx.x * blockDim.x + threadIdx.x;
    if (i < EE) atomicAdd(&g_deg[dst[i]], 1);
}

__global__ void scan_kernel() {
    __shared__ int wsum[32];
    __shared__ int s_base;
    int t = threadIdx.x, lane = t & 31, wid = t >> 5;
    if (t == 0) s_base = 0;
    __syncthreads();
    for (int base = 0; base < NN; base += 1024) {
        int i = base + t;
        int v = (i < NN) ? g_deg[i] : 0;
        int x = v;
        #pragma unroll
        for (int o = 1; o < 32; o <<= 1) {
            int y = __shfl_up_sync(0xffffffffu, x, o);
            if (lane >= o) x += y;
        }
        if (lane == 31) wsum[wid] = x;
        __syncthreads();
        if (wid == 0) {
            int w = wsum[lane];
            #pragma unroll
            for (int o = 1; o < 32; o <<= 1) {
                int y = __shfl_up_sync(0xffffffffu, w, o);
                if (lane >= o) w += y;
            }
            wsum[lane] = w;
        }
        __syncthreads();
        int excl = x - v + (wid ? wsum[wid - 1] : 0);
        if (i < NN) g_rowptr[i] = s_base + excl;
        int total = wsum[31];
        __syncthreads();
        if (t == 0) s_base += total;
        __syncthreads();
    }
    if (t == 0) g_rowptr[NN] = s_base;
}

__global__ void fill_kernel(const int* __restrict__ src, const int* __restrict__ dst) {
    int i = blockIdx.x * blockDim.x + threadIdx.x;
    if (i < EE) {
        int d = dst[i];
        int pos = g_rowptr[d] + atomicAdd(&g_cursor[d], 1);
        g_csrsrc[pos] = src[i];
    }
}

__global__ void roots_kernel(const int* __restrict__ batch) {
    int b = threadIdx.x;
    if (b > BB) return;
    if (b == BB) { g_root[BB] = NN; return; }
    int lo = 0, hi = NN;
    while (lo < hi) {
        int mid = (lo + hi) >> 1;
        if (batch[mid] < b) lo = mid + 1; else hi = mid;
    }
    g_root[b] = lo;
}

// ---------------- weight split: fp32 -> bf16 hi/lo, zero-padded to Kp rows ----------------
__global__ void convB_kernel(const float* __restrict__ W, __nv_bfloat16* __restrict__ hi,
                             __nv_bfloat16* __restrict__ lo, int K, int Kp) {
    int i = blockIdx.x * blockDim.x + threadIdx.x;
    if (i >= Kp * 128) return;
    int k = i >> 7;
    float v = (k < K) ? W[i] : 0.f;
    __nv_bfloat16 h = __float2bfloat16(v);
    hi[i] = h;
    lo[i] = __float2bfloat16(v - __bfloat162float(h));
}

// ---------------- tensor-core GEMM: C[M,128] = A[M,K] @ B[K,128] (bf16 split, 3 mma terms)
#define LDMX4(R, addr) \
    asm volatile("ldmatrix.sync.aligned.m8n8.x4.shared.b16 {%0,%1,%2,%3}, [%4];" \
        : "=r"((R)[0]), "=r"((R)[1]), "=r"((R)[2]), "=r"((R)[3]) : "r"(addr))
#define LDMX4T(r0, r1, r2, r3, addr) \
    asm volatile("ldmatrix.sync.aligned.m8n8.x4.trans.shared.b16 {%0,%1,%2,%3}, [%4];" \
        : "=r"(r0), "=r"(r1), "=r"(r2), "=r"(r3) : "r"(addr))
#define MMA16816(Cr, Ar, B0, B1) \
    asm volatile("mma.sync.aligned.m16n8k16.row.col.f32.bf16.bf16.f32 " \
        "{%0,%1,%2,%3},{%4,%5,%6,%7},{%8,%9},{%0,%1,%2,%3};" \
        : "+f"((Cr)[0]), "+f"((Cr)[1]), "+f"((Cr)[2]), "+f"((Cr)[3]) \
        : "r"((Ar)[0]), "r"((Ar)[1]), "r"((Ar)[2]), "r"((Ar)[3]), "r"(B0), "r"(B1))

__global__ __launch_bounds__(256) void gemm_tc(
    const float* __restrict__ A, const __nv_bfloat16* __restrict__ Bhi,
    const __nv_bfloat16* __restrict__ Blo, float* __restrict__ C,
    __half* __restrict__ Ch, int M, int K, int Kp)
{
    __shared__ __align__(16) __nv_bfloat16 sAhi[128][40];
    __shared__ __align__(16) __nv_bfloat16 sAlo[128][40];
    __shared__ __align__(16) __nv_bfloat16 sBhi[32][136];
    __shared__ __align__(16) __nv_bfloat16 sBlo[32][136];

    int tid = threadIdx.x;
    int lane = tid & 31, warp = tid >> 5;
    int wm = warp >> 2, wn = warp & 3;         // 2 x 4 warp grid; warp tile 64x32
    int row0 = blockIdx.x * 128;

    float acc[4][4][4];
    #pragma unroll
    for (int a = 0; a < 4; a++)
        #pragma unroll
        for (int b = 0; b < 4; b++)
            #pragma unroll
            for (int c = 0; c < 4; c++) acc[a][b][c] = 0.f;

    int lm = lane >> 3, lr = lane & 7;         // ldmatrix addressing

    for (int kt = 0; kt < Kp; kt += 32) {
        // fill A tile (fp32 gmem -> split bf16 smem); coalesced: warp reads one row
        #pragma unroll
        for (int i = 0; i < 16; i++) {
            int id = tid + i * 256;
            int r = id >> 5, c = id & 31;
            int gm = row0 + r, gk = kt + c;
            float v = (gm < M && gk < K) ? A[(long)gm * K + gk] : 0.f;
            __nv_bfloat16 h = __float2bfloat16(v);
            sAhi[r][c] = h;
            sAlo[r][c] = __float2bfloat16(v - __bfloat162float(h));
        }
        // fill B tiles (pre-split bf16, padded): 512 uint4 each
        {
            const uint4* bh = reinterpret_cast<const uint4*>(Bhi + kt * 128);
            const uint4* bl = reinterpret_cast<const uint4*>(Blo + kt * 128);
            #pragma unroll
            for (int i = 0; i < 2; i++) {
                int id = tid + i * 256;
                int r = id >> 4, c8 = id & 15;
                *reinterpret_cast<uint4*>(&sBhi[r][c8 * 8]) = bh[id];
                *reinterpret_cast<uint4*>(&sBlo[r][c8 * 8]) = bl[id];
            }
        }
        __syncthreads();

        #pragma unroll
        for (int k16 = 0; k16 < 2; k16++) {
            unsigned int ahi[4][4], alo[4][4], bhi[4][2], blo[4][2];
            #pragma unroll
            for (int mi = 0; mi < 4; mi++) {
                int rr = wm * 64 + mi * 16 + (lm & 1) * 8 + lr;
                int cc = k16 * 16 + (lm >> 1) * 8;
                unsigned int a0 = (unsigned int)__cvta_generic_to_shared(&sAhi[rr][cc]);
                LDMX4(ahi[mi], a0);
                unsigned int a1 = (unsigned int)__cvta_generic_to_shared(&sAlo[rr][cc]);
                LDMX4(alo[mi], a1);
            }
            #pragma unroll
            for (int np = 0; np < 2; np++) {
                int br = k16 * 16 + (lm & 1) * 8 + lr;
                int bc = wn * 32 + np * 16 + (lm >> 1) * 8;
                unsigned int ab = (unsigned int)__cvta_generic_to_shared(&sBhi[br][bc]);
                LDMX4T(bhi[2 * np][0], bhi[2 * np][1], bhi[2 * np + 1][0], bhi[2 * np + 1][1], ab);
                unsigned int al = (unsigned int)__cvta_generic_to_shared(&sBlo[br][bc]);
                LDMX4T(blo[2 * np][0], blo[2 * np][1], blo[2 * np + 1][0], blo[2 * np + 1][1], al);
            }
            #pragma unroll
            for (int mi = 0; mi < 4; mi++)
                #pragma unroll
                for (int nb = 0; nb < 4; nb++) {
                    MMA16816(acc[mi][nb], ahi[mi], bhi[nb][0], bhi[nb][1]);
                    MMA16816(acc[mi][nb], ahi[mi], blo[nb][0], blo[nb][1]);
                    MMA16816(acc[mi][nb], alo[mi], bhi[nb][0], bhi[nb][1]);
                }
        }
        __syncthreads();
    }

    // store fp32 + fp16 copies
    #pragma unroll
    for (int mi = 0; mi < 4; mi++) {
        int rb = row0 + wm * 64 + mi * 16 + (lane >> 2);
        #pragma unroll
        for (int nb = 0; nb < 4; nb++) {
            int cc = wn * 32 + nb * 8 + (lane & 3) * 2;
            if (rb < M) {
                *reinterpret_cast<float2*>(&C[(long)rb * 128 + cc]) =
                    make_float2(acc[mi][nb][0], acc[mi][nb][1]);
                *reinterpret_cast<__half2*>(&Ch[(long)rb * 128 + cc]) =
                    __floats2half2_rn(acc[mi][nb][0], acc[mi][nb][1]);
            }
            if (rb + 8 < M) {
                *reinterpret_cast<float2*>(&C[(long)(rb + 8) * 128 + cc]) =
                    make_float2(acc[mi][nb][2], acc[mi][nb][3]);
                *reinterpret_cast<__half2*>(&Ch[(long)(rb + 8) * 128 + cc]) =
                    __floats2half2_rn(acc[mi][nb][2], acc[mi][nb][3]);
            }
        }
    }
}

// ---------------- per-node attention logits ----------------
__global__ void alpha_kernel(const float* __restrict__ xw,
                             const float* __restrict__ a_src,
                             const float* __restrict__ a_dst) {
    int gw = (blockIdx.x * blockDim.x + threadIdx.x) >> 5;
    int lane = threadIdx.x & 31;
    if (gw >= NN) return;
    float4 v = *reinterpret_cast<const float4*>(&xw[gw * HD + lane * 4]);
    int head = lane >> 4;
    int ci = (lane * 4) & 63;
    float4 s4 = *reinterpret_cast<const float4*>(&a_src[head * 64 + ci]);
    float4 d4 = *reinterpret_cast<const float4*>(&a_dst[head * 64 + ci]);
    float ss = v.x * s4.x + v.y * s4.y + v.z * s4.z + v.w * s4.w;
    float dd = v.x * d4.x + v.y * d4.y + v.z * d4.z + v.w * d4.w;
    #pragma unroll
    for (int o = 8; o; o >>= 1) {
        ss += __shfl_down_sync(0xffffffffu, ss, o, 16);
        dd += __shfl_down_sync(0xffffffffu, dd, o, 16);
    }
    if ((lane & 15) == 0) {
        g_asrc[gw * 2 + head] = ss;
        g_adst[gw * 2 + head] = dd;
    }
}

// ---------------- GAT aggregation: warp per dst node (fp16 gathers) ----------------
__global__ void aggregate_kernel(const __half* __restrict__ xh,
                                 const float* __restrict__ bias,
                                 float* __restrict__ out) {
    int gw = (blockIdx.x * blockDim.x + threadIdx.x) >> 5;
    int lane = threadIdx.x & 31;
    if (gw >= NN) return;
    int i = gw;
    float ad0 = g_adst[2 * i], ad1 = g_adst[2 * i + 1];
    float es0 = lrelu(g_asrc[2 * i] + ad0);
    float es1 = lrelu(g_asrc[2 * i + 1] + ad1);
    int r0 = g_rowptr[i], r1 = g_rowptr[i + 1];

    // pass 1: max (self-loop included)
    float m0 = es0, m1 = es1;
    for (int j = r0 + lane; j < r1; j += 32) {
        int s = g_csrsrc[j];
        m0 = fmaxf(m0, lrelu(g_asrc[2 * s] + ad0));
        m1 = fmaxf(m1, lrelu(g_asrc[2 * s + 1] + ad1));
    }
    #pragma unroll
    for (int o = 16; o; o >>= 1) {
        m0 = fmaxf(m0, __shfl_xor_sync(0xffffffffu, m0, o));
        m1 = fmaxf(m1, __shfl_xor_sync(0xffffffffu, m1, o));
    }

    // pass 2: denominator
    float s0 = 0.f, s1 = 0.f;
    for (int j = r0 + lane; j < r1; j += 32) {
        int s = g_csrsrc[j];
        s0 += expf(lrelu(g_asrc[2 * s] + ad0) - m0);
        s1 += expf(lrelu(g_asrc[2 * s + 1] + ad1) - m1);
    }
    #pragma unroll
    for (int o = 16; o; o >>= 1) {
        s0 += __shfl_xor_sync(0xffffffffu, s0, o);
        s1 += __shfl_xor_sync(0xffffffffu, s1, o);
    }
    s0 += expf(es0 - m0);
    s1 += expf(es1 - m1);
    float inv0 = 1.f / (s0 + 1e-16f);
    float inv1 = 1.f / (s1 + 1e-16f);

    // pass 3: weighted message sum; lane covers cols [4*lane, 4*lane+4)
    int head = lane >> 4;
    float4 acc = make_float4(0.f, 0.f, 0.f, 0.f);
    for (int jb = r0; jb < r1; jb += 32) {
        int j = jb + lane;
        int s = 0; float w0 = 0.f, w1 = 0.f;
        if (j < r1) {
            s = g_csrsrc[j];
            w0 = expf(lrelu(g_asrc[2 * s] + ad0) - m0) * inv0;
            w1 = expf(lrelu(g_asrc[2 * s + 1] + ad1) - m1) * inv1;
        }
        int cnt = min(32, r1 - jb);
        for (int k = 0; k < cnt; k++) {
            int   sk  = __shfl_sync(0xffffffffu, s, k);
            float wk0 = __shfl_sync(0xffffffffu, w0, k);
            float wk1 = __shfl_sync(0xffffffffu, w1, k);
            float wk = head ? wk1 : wk0;
            uint2 raw = *reinterpret_cast<const uint2*>(&xh[(long)sk * HD + lane * 4]);
            __half2 p0 = *reinterpret_cast<__half2*>(&raw.x);
            __half2 p1 = *reinterpret_cast<__half2*>(&raw.y);
            float2 f0 = __half22float2(p0);
            float2 f1 = __half22float2(p1);
            acc.x = fmaf(wk, f0.x, acc.x);
            acc.y = fmaf(wk, f0.y, acc.y);
            acc.z = fmaf(wk, f1.x, acc.z);
            acc.w = fmaf(wk, f1.y, acc.w);
        }
    }
    float wself = head ? (expf(es1 - m1) * inv1) : (expf(es0 - m0) * inv0);
    {
        uint2 raw = *reinterpret_cast<const uint2*>(&xh[(long)i * HD + lane * 4]);
        __half2 p0 = *reinterpret_cast<__half2*>(&raw.x);
        __half2 p1 = *reinterpret_cast<__half2*>(&raw.y);
        float2 f0 = __half22float2(p0);
        float2 f1 = __half22float2(p1);
        acc.x = fmaf(wself, f0.x, acc.x);
        acc.y = fmaf(wself, f0.y, acc.y);
        acc.z = fmaf(wself, f1.x, acc.z);
        acc.w = fmaf(wself, f1.y, acc.w);
    }

    float4 b = *reinterpret_cast<const float4*>(&bias[lane * 4]);
    float4 o;
    o.x = fmaxf(acc.x + b.x, 0.f);
    o.y = fmaxf(acc.y + b.y, 0.f);
    o.z = fmaxf(acc.z + b.z, 0.f);
    o.w = fmaxf(acc.w + b.w, 0.f);
    *reinterpret_cast<float4*>(&out[i * HD + lane * 4]) = o;
}

// ---------------- pool + readout + news + concat + sigmoid ----------------
__global__ void head_kernel(const float* __restrict__ h, const float* __restrict__ x,
                            const float* __restrict__ Wr, const float* __restrict__ br,
                            const float* __restrict__ Wn, const float* __restrict__ bn,
                            const float* __restrict__ Wc, const float* __restrict__ bc,
                            float* __restrict__ out) {
    int b = blockIdx.x;
    int t = threadIdx.x;   // 128
    __shared__ float pooled[128];
    __shared__ float xroot[312];
    __shared__ float red[128];

    int r0 = g_root[b], r1 = g_root[b + 1];
    float s = 0.f;
    for (int n = r0; n < r1; n++) s += h[n * 128 + t];
    pooled[t] = s / (float)(r1 - r0);
    for (int k = t; k < IN_DIM; k += 128) xroot[k] = x[(long)r0 * IN_DIM + k];
    __syncthreads();

    float accg = br[t];
    #pragma unroll 4
    for (int k = 0; k < 128; k++) accg = fmaf(pooled[k], Wr[k * 128 + t], accg);
    float g = fmaxf(accg, 0.f);

    float accn = bn[t];
    for (int k = 0; k < IN_DIM; k++) accn = fmaf(xroot[k], Wn[k * 128 + t], accn);
    float nws = fmaxf(accn, 0.f);

    red[t] = g * Wc[t] + nws * Wc[128 + t];
    __syncthreads();
    for (int o = 64; o; o >>= 1) {
        if (t < o) red[t] += red[t + o];
        __syncthreads();
    }
    if (t == 0) out[b] = 1.f / (1.f + expf(-(red[0] + bc[0])));
}

// ---------------- launch ----------------
extern "C" void kernel_launch(void* const* d_in, const int* in_sizes, int n_in,
                              void* d_out, int out_size) {
    const float* x   = (const float*)d_in[0];
    const float* W0  = (const float*)d_in[1];
    const float* as0 = (const float*)d_in[2];
    const float* ad0 = (const float*)d_in[3];
    const float* b0  = (const float*)d_in[4];
    const float* W1  = (const float*)d_in[5];
    const float* as1 = (const float*)d_in[6];
    const float* ad1 = (const float*)d_in[7];
    const float* b1  = (const float*)d_in[8];
    const float* Wn  = (const float*)d_in[9];
    const float* bn  = (const float*)d_in[10];
    const float* Wr  = (const float*)d_in[11];
    const float* br  = (const float*)d_in[12];
    const float* Wc  = (const float*)d_in[13];
    const float* bc  = (const float*)d_in[14];
    const int*   ei  = (const int*)d_in[15];
    const int*   batch = (const int*)d_in[16];
    float* out = (float*)d_out;

    const int* src = ei;
    const int* dst = ei + EE;

    void *p_xw, *p_xwh, *p_h, *p_bh0, *p_bl0, *p_bh1, *p_bl1;
    cudaGetSymbolAddress(&p_xw, g_xw);
    cudaGetSymbolAddress(&p_xwh, g_xwh);
    cudaGetSymbolAddress(&p_h, g_h);
    cudaGetSymbolAddress(&p_bh0, g_Bhi0);
    cudaGetSymbolAddress(&p_bl0, g_Blo0);
    cudaGetSymbolAddress(&p_bh1, g_Bhi1);
    cudaGetSymbolAddress(&p_bl1, g_Blo1);
    float* xw = (float*)p_xw;
    __half* xwh = (__half*)p_xwh;
    float* hbuf = (float*)p_h;

    // weight splits
    convB_kernel<<<(KP0 * 128 + 255) / 256, 256>>>(W0, (__nv_bfloat16*)p_bh0, (__nv_bfloat16*)p_bl0, IN_DIM, KP0);
    convB_kernel<<<(128 * 128 + 255) / 256, 256>>>(W1, (__nv_bfloat16*)p_bh1, (__nv_bfloat16*)p_bl1, 128, 128);

    // CSR build (reused for both GAT layers)
    zero_kernel<<<(NN + 255) / 256, 256>>>();
    count_kernel<<<(EE + 255) / 256, 256>>>(dst);
    scan_kernel<<<1, 1024>>>();
    fill_kernel<<<(EE + 255) / 256, 256>>>(src, dst);
    roots_kernel<<<1, 256>>>(batch);

    // GAT layer 0
    gemm_tc<<<(NN + 127) / 128, 256>>>(x, (__nv_bfloat16*)p_bh0, (__nv_bfloat16*)p_bl0,
                                       xw, xwh, NN, IN_DIM, KP0);
    alpha_kernel<<<(NN + 7) / 8, 256>>>(xw, as0, ad0);
    aggregate_kernel<<<(NN + 7) / 8, 256>>>(xwh, b0, hbuf);

    // GAT layer 1
    gemm_tc<<<(NN + 127) / 128, 256>>>(hbuf, (__nv_bfloat16*)p_bh1, (__nv_bfloat16*)p_bl1,
                                       xw, xwh, NN, 128, 128);
    alpha_kernel<<<(NN + 7) / 8, 256>>>(xw, as1, ad1);
    aggregate_kernel<<<(NN + 7) / 8, 256>>>(xwh, b1, hbuf);

    // pooling + readout + news + concat + sigmoid
    head_kernel<<<BB, 128>>>(hbuf, x, Wr, br, Wn, bn, Wc, bc, out);
}

// round 4
// speedup vs baseline: 1.8638x; 1.2151x over previous
#include <cuda_runtime.h>
#include <cuda_fp16.h>
#include <stdint.h>
#include <math.h>

// Problem constants (fixed shapes for this dataset)
#define NN 50000
#define EE 800000
#define BB 128
#define IN_DIM 310
#define KP0 320      // IN_DIM padded to multiple of 32
#define HD 128       // 2 heads x 64
#define NH 2

// ---------------- scratch (static device globals; no allocation) ----------------
__device__ __align__(16) __half g_xwh[NN * HD];      // GEMM output fp16 (for gather)
__device__ __align__(16) float g_h[NN * HD];         // aggregated layer output
__device__ float g_asrc[NN * NH];
__device__ float g_adst[NN * NH];
__device__ int   g_deg[NN];
__device__ int   g_cursor[NN];
__device__ int   g_rowptr[NN + 1];
__device__ int   g_csrsrc[EE];
__device__ int   g_root[BB + 1];
// tf32-rounded weight matrices, zero-padded along K
__device__ __align__(16) float g_B0[KP0 * 128];
__device__ __align__(16) float g_B1[128 * 128];

__device__ __forceinline__ float lrelu(float z) { return z > 0.f ? z : 0.2f * z; }
__device__ __forceinline__ float to_tf32(float x) {
    float r;
    asm("cvt.rna.tf32.f32 %0, %1;" : "=f"(r) : "f"(x));
    return r;
}

// ---------------- CSR build ----------------
__global__ void zero_csr_kernel() {
    int i = blockIdx.x * blockDim.x + threadIdx.x;
    if (i < NN) { g_deg[i] = 0; g_cursor[i] = 0; }
}

__global__ void zero_alpha_kernel() {
    int i = blockIdx.x * blockDim.x + threadIdx.x;
    if (i < NN * NH) { g_asrc[i] = 0.f; g_adst[i] = 0.f; }
}

__global__ void count_kernel(const int* __restrict__ dst) {
    int i = blockIdx.x * blockDim.x + threadIdx.x;
    if (i < EE) atomicAdd(&g_deg[dst[i]], 1);
}

// chunked scan: 1024 threads, each owns a contiguous chunk
__global__ void scan_kernel() {
    const int CH = (NN + 1023) / 1024;     // 49
    __shared__ int ws[32];
    int t = threadIdx.x, lane = t & 31, wid = t >> 5;
    int lo = t * CH, hi = min(lo + CH, NN);
    if (lo > NN) lo = NN;
    if (hi < lo) hi = lo;
    int sum = 0;
    for (int i = lo; i < hi; i++) sum += g_deg[i];
    int x = sum;
    #pragma unroll
    for (int o = 1; o < 32; o <<= 1) {
        int y = __shfl_up_sync(0xffffffffu, x, o);
        if (lane >= o) x += y;
    }
    if (lane == 31) ws[wid] = x;
    __syncthreads();
    if (wid == 0) {
        int w = ws[lane];
        #pragma unroll
        for (int o = 1; o < 32; o <<= 1) {
            int y = __shfl_up_sync(0xffffffffu, w, o);
            if (lane >= o) w += y;
        }
        ws[lane] = w;
    }
    __syncthreads();
    int run = x - sum + (wid ? ws[wid - 1] : 0);
    for (int i = lo; i < hi; i++) { g_rowptr[i] = run; run += g_deg[i]; }
    if (t == 1023) g_rowptr[NN] = run;
}

__global__ void fill_kernel(const int* __restrict__ src, const int* __restrict__ dst) {
    int i = blockIdx.x * blockDim.x + threadIdx.x;
    if (i < EE) {
        int d = dst[i];
        int pos = g_rowptr[d] + atomicAdd(&g_cursor[d], 1);
        g_csrsrc[pos] = src[i];
    }
}

__global__ void roots_kernel(const int* __restrict__ batch) {
    int b = threadIdx.x;
    if (b > BB) return;
    if (b == BB) { g_root[BB] = NN; return; }
    int lo = 0, hi = NN;
    while (lo < hi) {
        int mid = (lo + hi) >> 1;
        if (batch[mid] < b) lo = mid + 1; else hi = mid;
    }
    g_root[b] = lo;
}

// ---------------- weight prep: fp32 -> tf32-rounded fp32, zero-padded ----------------
__global__ void convB_kernel(const float* __restrict__ W, float* __restrict__ outB,
                             int K, int Kp) {
    int i = blockIdx.x * blockDim.x + threadIdx.x;
    if (i >= Kp * 128) return;
    int k = i >> 7;
    float v = (k < K) ? W[i] : 0.f;
    outB[i] = to_tf32(v);
}

// ---------------- tf32 tensor-core GEMM with fused alpha epilogue ----------------
// C[M,128] = A[M,K] @ B[K,128]; writes fp16 copy + atomically accumulates
// alpha_src/alpha_dst = sum_c C[i,c] * a{S,D}[c] per head into g_asrc/g_adst.
#define MMA_TF32(Cr, a0, a1, a2, a3, b0, b1) \
    asm volatile("mma.sync.aligned.m16n8k8.row.col.f32.tf32.tf32.f32 " \
        "{%0,%1,%2,%3},{%4,%5,%6,%7},{%8,%9},{%0,%1,%2,%3};" \
        : "+f"((Cr)[0]), "+f"((Cr)[1]), "+f"((Cr)[2]), "+f"((Cr)[3]) \
        : "r"(a0), "r"(a1), "r"(a2), "r"(a3), "r"(b0), "r"(b1))

__global__ __launch_bounds__(256) void gemm_tf32(
    const float* __restrict__ A, const float* __restrict__ Bm,
    __half* __restrict__ Ch,
    const float* __restrict__ aS, const float* __restrict__ aD,
    int M, int K, int Kp)
{
    __shared__ float sA[128][36];   // stride 36: banks 4r+c, conflict-free frags
    __shared__ float sB[32][136];   // stride 136: banks 8k+g, conflict-free frags

    int tid = threadIdx.x;
    int lane = tid & 31, warp = tid >> 5;
    int wm = warp >> 2, wn = warp & 3;   // 2 x 4 warps; warp tile 64 x 32
    int row0 = blockIdx.x * 128;
    int gq = lane >> 2, tq = lane & 3;   // groupID / threadID-in-group

    float acc[4][4][4];
    #pragma unroll
    for (int a = 0; a < 4; a++)
        #pragma unroll
        for (int b = 0; b < 4; b++)
            #pragma unroll
            for (int c = 0; c < 4; c++) acc[a][b][c] = 0.f;

    for (int kt = 0; kt < Kp; kt += 32) {
        // A tile: 128x32, coalesced, tf32-round on the way in
        #pragma unroll
        for (int i = 0; i < 16; i++) {
            int id = tid + i * 256;
            int r = id >> 5, c = id & 31;
            int gm = row0 + r, gk = kt + c;
            float v = (gm < M && gk < K) ? A[(long)gm * K + gk] : 0.f;
            sA[r][c] = to_tf32(v);
        }
        // B tile: 32x128, already tf32-rounded + padded
        #pragma unroll
        for (int i = 0; i < 16; i++) {
            int id = tid + i * 256;
            int r = id >> 7, c = id & 127;
            sB[r][c] = Bm[(kt + r) * 128 + c];
        }
        __syncthreads();

        #pragma unroll
        for (int ks = 0; ks < 4; ks++) {
            int c0 = ks * 8 + tq;
            unsigned int af[4][4];
            #pragma unroll
            for (int mi = 0; mi < 4; mi++) {
                int r = wm * 64 + mi * 16 + gq;
                af[mi][0] = __float_as_uint(sA[r][c0]);
                af[mi][1] = __float_as_uint(sA[r + 8][c0]);
                af[mi][2] = __float_as_uint(sA[r][c0 + 4]);
                af[mi][3] = __float_as_uint(sA[r + 8][c0 + 4]);
            }
            unsigned int bf[4][2];
            #pragma unroll
            for (int nb = 0; nb < 4; nb++) {
                int n = wn * 32 + nb * 8 + gq;
                bf[nb][0] = __float_as_uint(sB[ks * 8 + tq][n]);
                bf[nb][1] = __float_as_uint(sB[ks * 8 + 4 + tq][n]);
            }
            #pragma unroll
            for (int mi = 0; mi < 4; mi++)
                #pragma unroll
                for (int nb = 0; nb < 4; nb++)
                    MMA_TF32(acc[mi][nb], af[mi][0], af[mi][1], af[mi][2], af[mi][3],
                             bf[nb][0], bf[nb][1]);
        }
        __syncthreads();
    }

    // epilogue: fp16 store + fused alpha partial reduction
    int head = wn >> 1;
    #pragma unroll
    for (int mi = 0; mi < 4; mi++) {
        int rb = row0 + wm * 64 + mi * 16 + gq;
        float s_lo = 0.f, s_hi = 0.f, d_lo = 0.f, d_hi = 0.f;
        #pragma unroll
        for (int nb = 0; nb < 4; nb++) {
            int cc = wn * 32 + nb * 8 + tq * 2;
            float as0 = aS[cc], as1 = aS[cc + 1];
            float ad0 = aD[cc], ad1 = aD[cc + 1];
            s_lo += acc[mi][nb][0] * as0 + acc[mi][nb][1] * as1;
            d_lo += acc[mi][nb][0] * ad0 + acc[mi][nb][1] * ad1;
            s_hi += acc[mi][nb][2] * as0 + acc[mi][nb][3] * as1;
            d_hi += acc[mi][nb][2] * ad0 + acc[mi][nb][3] * ad1;
            if (rb < M)
                *reinterpret_cast<__half2*>(&Ch[(long)rb * 128 + cc]) =
                    __floats2half2_rn(acc[mi][nb][0], acc[mi][nb][1]);
            if (rb + 8 < M)
                *reinterpret_cast<__half2*>(&Ch[(long)(rb + 8) * 128 + cc]) =
                    __floats2half2_rn(acc[mi][nb][2], acc[mi][nb][3]);
        }
        if (rb < M) {
            atomicAdd(&g_asrc[2 * rb + head], s_lo);
            atomicAdd(&g_adst[2 * rb + head], d_lo);
        }
        if (rb + 8 < M) {
            atomicAdd(&g_asrc[2 * (rb + 8) + head], s_hi);
            atomicAdd(&g_adst[2 * (rb + 8) + head], d_hi);
        }
    }
}

// ---------------- GAT aggregation: warp per dst node, cached logits ----------------
__global__ void aggregate_kernel(const __half* __restrict__ xh,
                                 const float* __restrict__ bias,
                                 float* __restrict__ out) {
    int gw = (blockIdx.x * blockDim.x + threadIdx.x) >> 5;
    int lane = threadIdx.x & 31;
    if (gw >= NN) return;
    int i = gw;
    float ad0 = g_adst[2 * i], ad1 = g_adst[2 * i + 1];
    float es0 = lrelu(g_asrc[2 * i] + ad0);
    float es1 = lrelu(g_asrc[2 * i + 1] + ad1);
    int r0 = g_rowptr[i], r1 = g_rowptr[i + 1];

    const float NEG = -1e30f;
    int sc[4]; float e0c[4], e1c[4];
    float m0 = es0, m1 = es1;

    // pass 1: compute logits for first 4 strips (cached) + max
    #pragma unroll
    for (int q = 0; q < 4; q++) {
        int j = r0 + q * 32 + lane;
        if (j < r1) {
            int s = g_csrsrc[j];
            float e0 = lrelu(g_asrc[2 * s] + ad0);
            float e1 = lrelu(g_asrc[2 * s + 1] + ad1);
            sc[q] = s; e0c[q] = e0; e1c[q] = e1;
            m0 = fmaxf(m0, e0); m1 = fmaxf(m1, e1);
        } else { sc[q] = 0; e0c[q] = NEG; e1c[q] = NEG; }
    }
    for (int j = r0 + 128 + lane; j < r1; j += 32) {
        int s = g_csrsrc[j];
        m0 = fmaxf(m0, lrelu(g_asrc[2 * s] + ad0));
        m1 = fmaxf(m1, lrelu(g_asrc[2 * s + 1] + ad1));
    }
    #pragma unroll
    for (int o = 16; o; o >>= 1) {
        m0 = fmaxf(m0, __shfl_xor_sync(0xffffffffu, m0, o));
        m1 = fmaxf(m1, __shfl_xor_sync(0xffffffffu, m1, o));
    }

    // pass 2: denominator
    float s0 = 0.f, s1 = 0.f;
    #pragma unroll
    for (int q = 0; q < 4; q++) {
        s0 += __expf(e0c[q] - m0);
        s1 += __expf(e1c[q] - m1);
    }
    for (int j = r0 + 128 + lane; j < r1; j += 32) {
        int s = g_csrsrc[j];
        s0 += __expf(lrelu(g_asrc[2 * s] + ad0) - m0);
        s1 += __expf(lrelu(g_asrc[2 * s + 1] + ad1) - m1);
    }
    #pragma unroll
    for (int o = 16; o; o >>= 1) {
        s0 += __shfl_xor_sync(0xffffffffu, s0, o);
        s1 += __shfl_xor_sync(0xffffffffu, s1, o);
    }
    s0 += __expf(es0 - m0);
    s1 += __expf(es1 - m1);
    float inv0 = 1.f / (s0 + 1e-16f);
    float inv1 = 1.f / (s1 + 1e-16f);

    // pass 3: weighted message sum; lane covers cols [4*lane, 4*lane+4)
    int head = lane >> 4;
    float4 acc = make_float4(0.f, 0.f, 0.f, 0.f);
    // cached strips
    #pragma unroll
    for (int q = 0; q < 4; q++) {
        if (r0 + q * 32 >= r1) break;
        int s = sc[q];
        float w0 = __expf(e0c[q] - m0) * inv0;
        float w1 = __expf(e1c[q] - m1) * inv1;
        int cnt = min(32, r1 - (r0 + q * 32));
        for (int k = 0; k < cnt; k++) {
            int   sk  = __shfl_sync(0xffffffffu, s, k);
            float wk0 = __shfl_sync(0xffffffffu, w0, k);
            float wk1 = __shfl_sync(0xffffffffu, w1, k);
            float wk = head ? wk1 : wk0;
            uint2 raw = *reinterpret_cast<const uint2*>(&xh[(long)sk * HD + lane * 4]);
            __half2 p0 = *reinterpret_cast<__half2*>(&raw.x);
            __half2 p1 = *reinterpret_cast<__half2*>(&raw.y);
            float2 f0 = __half22float2(p0);
            float2 f1 = __half22float2(p1);
            acc.x = fmaf(wk, f0.x, acc.x);
            acc.y = fmaf(wk, f0.y, acc.y);
            acc.z = fmaf(wk, f1.x, acc.z);
            acc.w = fmaf(wk, f1.y, acc.w);
        }
    }
    // remainder strips (recompute logits)
    for (int jb = r0 + 128; jb < r1; jb += 32) {
        int j = jb + lane;
        int s = 0; float w0 = 0.f, w1 = 0.f;
        if (j < r1) {
            s = g_csrsrc[j];
            w0 = __expf(lrelu(g_asrc[2 * s] + ad0) - m0) * inv0;
            w1 = __expf(lrelu(g_asrc[2 * s + 1] + ad1) - m1) * inv1;
        }
        int cnt = min(32, r1 - jb);
        for (int k = 0; k < cnt; k++) {
            int   sk  = __shfl_sync(0xffffffffu, s, k);
            float wk0 = __shfl_sync(0xffffffffu, w0, k);
            float wk1 = __shfl_sync(0xffffffffu, w1, k);
            float wk = head ? wk1 : wk0;
            uint2 raw = *reinterpret_cast<const uint2*>(&xh[(long)sk * HD + lane * 4]);
            __half2 p0 = *reinterpret_cast<__half2*>(&raw.x);
            __half2 p1 = *reinterpret_cast<__half2*>(&raw.y);
            float2 f0 = __half22float2(p0);
            float2 f1 = __half22float2(p1);
            acc.x = fmaf(wk, f0.x, acc.x);
            acc.y = fmaf(wk, f0.y, acc.y);
            acc.z = fmaf(wk, f1.x, acc.z);
            acc.w = fmaf(wk, f1.y, acc.w);
        }
    }
    // self loop
    float wself = head ? (__expf(es1 - m1) * inv1) : (__expf(es0 - m0) * inv0);
    {
        uint2 raw = *reinterpret_cast<const uint2*>(&xh[(long)i * HD + lane * 4]);
        __half2 p0 = *reinterpret_cast<__half2*>(&raw.x);
        __half2 p1 = *reinterpret_cast<__half2*>(&raw.y);
        float2 f0 = __half22float2(p0);
        float2 f1 = __half22float2(p1);
        acc.x = fmaf(wself, f0.x, acc.x);
        acc.y = fmaf(wself, f0.y, acc.y);
        acc.z = fmaf(wself, f1.x, acc.z);
        acc.w = fmaf(wself, f1.y, acc.w);
    }

    float4 b = *reinterpret_cast<const float4*>(&bias[lane * 4]);
    float4 o;
    o.x = fmaxf(acc.x + b.x, 0.f);
    o.y = fmaxf(acc.y + b.y, 0.f);
    o.z = fmaxf(acc.z + b.z, 0.f);
    o.w = fmaxf(acc.w + b.w, 0.f);
    *reinterpret_cast<float4*>(&out[i * HD + lane * 4]) = o;
}

// ---------------- pool + readout + news + concat + sigmoid ----------------
__global__ void head_kernel(const float* __restrict__ h, const float* __restrict__ x,
                            const float* __restrict__ Wr, const float* __restrict__ br,
                            const float* __restrict__ Wn, const float* __restrict__ bn,
                            const float* __restrict__ Wc, const float* __restrict__ bc,
                            float* __restrict__ out) {
    int b = blockIdx.x;
    int t = threadIdx.x;   // 128
    __shared__ float pooled[128];
    __shared__ float xroot[312];
    __shared__ float red[128];

    int r0 = g_root[b], r1 = g_root[b + 1];
    float s = 0.f;
    for (int n = r0; n < r1; n++) s += h[n * 128 + t];
    pooled[t] = s / (float)(r1 - r0);
    for (int k = t; k < IN_DIM; k += 128) xroot[k] = x[(long)r0 * IN_DIM + k];
    __syncthreads();

    float accg = br[t];
    #pragma unroll 4
    for (int k = 0; k < 128; k++) accg = fmaf(pooled[k], Wr[k * 128 + t], accg);
    float g = fmaxf(accg, 0.f);

    float accn = bn[t];
    for (int k = 0; k < IN_DIM; k++) accn = fmaf(xroot[k], Wn[k * 128 + t], accn);
    float nws = fmaxf(accn, 0.f);

    red[t] = g * Wc[t] + nws * Wc[128 + t];
    __syncthreads();
    for (int o = 64; o; o >>= 1) {
        if (t < o) red[t] += red[t + o];
        __syncthreads();
    }
    if (t == 0) out[b] = 1.f / (1.f + expf(-(red[0] + bc[0])));
}

// ---------------- launch ----------------
extern "C" void kernel_launch(void* const* d_in, const int* in_sizes, int n_in,
                              void* d_out, int out_size) {
    const float* x   = (const float*)d_in[0];
    const float* W0  = (const float*)d_in[1];
    const float* as0 = (const float*)d_in[2];
    const float* ad0 = (const float*)d_in[3];
    const float* b0  = (const float*)d_in[4];
    const float* W1  = (const float*)d_in[5];
    const float* as1 = (const float*)d_in[6];
    const float* ad1 = (const float*)d_in[7];
    const float* b1  = (const float*)d_in[8];
    const float* Wn  = (const float*)d_in[9];
    const float* bn  = (const float*)d_in[10];
    const float* Wr  = (const float*)d_in[11];
    const float* br  = (const float*)d_in[12];
    const float* Wc  = (const float*)d_in[13];
    const float* bc  = (const float*)d_in[14];
    const int*   ei  = (const int*)d_in[15];
    const int*   batch = (const int*)d_in[16];
    float* out = (float*)d_out;

    const int* src = ei;
    const int* dst = ei + EE;

    void *p_xwh, *p_h, *p_b0, *p_b1;
    cudaGetSymbolAddress(&p_xwh, g_xwh);
    cudaGetSymbolAddress(&p_h, g_h);
    cudaGetSymbolAddress(&p_b0, g_B0);
    cudaGetSymbolAddress(&p_b1, g_B1);
    __half* xwh = (__half*)p_xwh;
    float* hbuf = (float*)p_h;

    // side stream + fork/join events (created once; capture-safe pattern)
    static cudaStream_t s1 = nullptr;
    static cudaEvent_t evFork = nullptr, evJoin = nullptr;
    if (s1 == nullptr) {
        cudaStreamCreateWithFlags(&s1, cudaStreamNonBlocking);
        cudaEventCreateWithFlags(&evFork, cudaEventDisableTiming);
        cudaEventCreateWithFlags(&evJoin, cudaEventDisableTiming);
    }

    // fork: CSR build on s1 runs concurrently with weight prep + GEMM0 on s0
    cudaEventRecord(evFork, 0);
    cudaStreamWaitEvent(s1, evFork, 0);

    zero_csr_kernel<<<(NN + 255) / 256, 256, 0, s1>>>();
    count_kernel<<<(EE + 255) / 256, 256, 0, s1>>>(dst);
    scan_kernel<<<1, 1024, 0, s1>>>();
    fill_kernel<<<(EE + 255) / 256, 256, 0, s1>>>(src, dst);
    roots_kernel<<<1, 256, 0, s1>>>(batch);
    cudaEventRecord(evJoin, s1);

    // s0: weight prep + GEMM0 (fused alpha)
    convB_kernel<<<(KP0 * 128 + 255) / 256, 256>>>(W0, (float*)p_b0, IN_DIM, KP0);
    convB_kernel<<<(128 * 128 + 255) / 256, 256>>>(W1, (float*)p_b1, 128, 128);
    zero_alpha_kernel<<<(NN * NH + 255) / 256, 256>>>();
    gemm_tf32<<<(NN + 127) / 128, 256>>>(x, (float*)p_b0, xwh, as0, ad0, NN, IN_DIM, KP0);

    // join: aggregation needs both CSR and GEMM0
    cudaStreamWaitEvent(0, evJoin, 0);

    aggregate_kernel<<<(NN + 7) / 8, 256>>>(xwh, b0, hbuf);

    // GAT layer 1
    zero_alpha_kernel<<<(NN * NH + 255) / 256, 256>>>();
    gemm_tf32<<<(NN + 127) / 128, 256>>>(hbuf, (float*)p_b1, xwh, as1, ad1, NN, 128, 128);
    aggregate_kernel<<<(NN + 7) / 8, 256>>>(xwh, b1, hbuf);

    // pooling + readout + news + concat + sigmoid
    head_kernel<<<BB, 128>>>(hbuf, x, Wr, br, Wn, bn, Wc, bc, out);
}

// round 6
// speedup vs baseline: 2.0082x; 1.0774x over previous
#include <cuda_runtime.h>
#include <cuda_fp16.h>
#include <stdint.h>
#include <math.h>

// Problem constants (fixed shapes for this dataset)
#define NN 50000
#define EE 800000
#define BB 128
#define IN_DIM 310
#define KP0 320      // IN_DIM padded to multiple of 32
#define HD 128       // 2 heads x 64
#define NH 2

// ---------------- scratch (static device globals; no allocation) ----------------
__device__ __align__(16) __half g_xwh[NN * HD];      // GEMM output fp16 (for gather)
__device__ __align__(16) float g_h[NN * HD];         // aggregated layer output
__device__ float g_asrc[NN * NH];
__device__ float g_adst[NN * NH];
__device__ int   g_deg[NN];
__device__ int   g_cursor[NN];
__device__ int   g_rowptr[NN + 1];
__device__ int   g_csrsrc[EE];
__device__ int   g_root[BB + 1];
__device__ __align__(16) float g_pooled[BB * 128];
// tf32-rounded weight matrices, zero-padded along K
__device__ __align__(16) float g_B0[KP0 * 128];
__device__ __align__(16) float g_B1[128 * 128];

__device__ __forceinline__ float lrelu(float z) { return z > 0.f ? z : 0.2f * z; }
__device__ __forceinline__ float to_tf32(float x) {
    float r;
    asm("cvt.rna.tf32.f32 %0, %1;" : "=f"(r) : "f"(x));
    return r;
}

// ---------------- CSR build ----------------
__global__ void zero_csr_kernel() {
    int i = blockIdx.x * blockDim.x + threadIdx.x;
    if (i < NN) { g_deg[i] = 0; g_cursor[i] = 0; }
}

__global__ void zero_alpha_kernel() {
    int i = blockIdx.x * blockDim.x + threadIdx.x;
    if (i < NN * NH) { g_asrc[i] = 0.f; g_adst[i] = 0.f; }
}

__global__ void count_kernel(const int* __restrict__ dst) {
    int i = blockIdx.x * blockDim.x + threadIdx.x;
    if (i < EE / 4) {
        int4 d = reinterpret_cast<const int4*>(dst)[i];
        atomicAdd(&g_deg[d.x], 1);
        atomicAdd(&g_deg[d.y], 1);
        atomicAdd(&g_deg[d.z], 1);
        atomicAdd(&g_deg[d.w], 1);
    }
}

// chunked scan: 1024 threads, each owns a contiguous chunk
__global__ void scan_kernel() {
    const int CH = (NN + 1023) / 1024;     // 49
    __shared__ int ws[32];
    int t = threadIdx.x, lane = t & 31, wid = t >> 5;
    int lo = t * CH, hi = min(lo + CH, NN);
    if (lo > NN) lo = NN;
    if (hi < lo) hi = lo;
    int sum = 0;
    for (int i = lo; i < hi; i++) sum += g_deg[i];
    int x = sum;
    #pragma unroll
    for (int o = 1; o < 32; o <<= 1) {
        int y = __shfl_up_sync(0xffffffffu, x, o);
        if (lane >= o) x += y;
    }
    if (lane == 31) ws[wid] = x;
    __syncthreads();
    if (wid == 0) {
        int w = ws[lane];
        #pragma unroll
        for (int o = 1; o < 32; o <<= 1) {
            int y = __shfl_up_sync(0xffffffffu, w, o);
            if (lane >= o) w += y;
        }
        ws[lane] = w;
    }
    __syncthreads();
    int run = x - sum + (wid ? ws[wid - 1] : 0);
    for (int i = lo; i < hi; i++) { g_rowptr[i] = run; run += g_deg[i]; }
    if (t == 1023) g_rowptr[NN] = run;
}

__global__ void fill_kernel(const int* __restrict__ src, const int* __restrict__ dst) {
    int i = blockIdx.x * blockDim.x + threadIdx.x;
    if (i < EE / 4) {
        int4 s4 = reinterpret_cast<const int4*>(src)[i];
        int4 d4 = reinterpret_cast<const int4*>(dst)[i];
        int p0 = g_rowptr[d4.x] + atomicAdd(&g_cursor[d4.x], 1);
        int p1 = g_rowptr[d4.y] + atomicAdd(&g_cursor[d4.y], 1);
        int p2 = g_rowptr[d4.z] + atomicAdd(&g_cursor[d4.z], 1);
        int p3 = g_rowptr[d4.w] + atomicAdd(&g_cursor[d4.w], 1);
        g_csrsrc[p0] = s4.x;
        g_csrsrc[p1] = s4.y;
        g_csrsrc[p2] = s4.z;
        g_csrsrc[p3] = s4.w;
    }
}

__global__ void roots_kernel(const int* __restrict__ batch) {
    int b = threadIdx.x;
    if (b > BB) return;
    if (b == BB) { g_root[BB] = NN; return; }
    int lo = 0, hi = NN;
    while (lo < hi) {
        int mid = (lo + hi) >> 1;
        if (batch[mid] < b) lo = mid + 1; else hi = mid;
    }
    g_root[b] = lo;
}

// ---------------- weight prep: fp32 -> tf32-rounded fp32, zero-padded ----------------
__global__ void convB_kernel(const float* __restrict__ W, float* __restrict__ outB,
                             int K, int Kp) {
    int i = blockIdx.x * blockDim.x + threadIdx.x;
    if (i >= Kp * 128) return;
    int k = i >> 7;
    float v = (k < K) ? W[i] : 0.f;
    outB[i] = to_tf32(v);
}

// ---------------- tf32 tensor-core GEMM, cp.async double-buffered, fused alpha ----
#define MMA_TF32(Cr, a0, a1, a2, a3, b0, b1) \
    asm volatile("mma.sync.aligned.m16n8k8.row.col.f32.tf32.tf32.f32 " \
        "{%0,%1,%2,%3},{%4,%5,%6,%7},{%8,%9},{%0,%1,%2,%3};" \
        : "+f"((Cr)[0]), "+f"((Cr)[1]), "+f"((Cr)[2]), "+f"((Cr)[3]) \
        : "r"(a0), "r"(a1), "r"(a2), "r"(a3), "r"(b0), "r"(b1))
// A path: 8-byte cp.async (src only guaranteed 8B-aligned: row stride K*4 = 1240B)
#define CP8(dst, src, bytes) \
    asm volatile("cp.async.ca.shared.global [%0], [%1], 8, %2;" \
        :: "r"(dst), "l"(src), "r"(bytes))
// B path: 16-byte cp.async (row stride 512B, always 16B-aligned)
#define CP16(dst, src) \
    asm volatile("cp.async.cg.shared.global [%0], [%1], 16;" \
        :: "r"(dst), "l"(src))
#define CP_COMMIT() asm volatile("cp.async.commit_group;")
#define CP_WAIT(n)  asm volatile("cp.async.wait_group %0;" :: "n"(n))

#define SA_STRIDE 36
#define SB_STRIDE 136
#define SA_ELEMS (128 * SA_STRIDE)
#define SB_ELEMS (32 * SB_STRIDE)
#define GEMM_SMEM_BYTES ((2 * SA_ELEMS + 2 * SB_ELEMS) * 4)

__global__ __launch_bounds__(256) void gemm_tf32(
    const float* __restrict__ A, const float* __restrict__ Bm,
    __half* __restrict__ Ch,
    const float* __restrict__ aS, const float* __restrict__ aD,
    int M, int K, int Kp)
{
    extern __shared__ float smem[];
    float* sA = smem;                       // [2][128][36]
    float* sB = smem + 2 * SA_ELEMS;        // [2][32][136]

    int tid = threadIdx.x;
    int lane = tid & 31, warp = tid >> 5;
    int wm = warp >> 2, wn = warp & 3;   // 2 x 4 warps; warp tile 64 x 32
    int row0 = blockIdx.x * 128;
    int gq = lane >> 2, tq = lane & 3;

    float acc[4][4][4];
    #pragma unroll
    for (int a = 0; a < 4; a++)
        #pragma unroll
        for (int b = 0; b < 4; b++)
            #pragma unroll
            for (int c = 0; c < 4; c++) acc[a][b][c] = 0.f;

    unsigned sA_base = (unsigned)__cvta_generic_to_shared(sA);
    unsigned sB_base = (unsigned)__cvta_generic_to_shared(sB);
    int T = Kp / 32;

    // async tile loader: A via 8B chunks (alignment-safe), B via 16B chunks
    auto issue = [&](int t, int buf) {
        int kt = t * 32;
        // A: 2048 8B-chunks; thread gets 8 (16 chunks per 32-float row)
        #pragma unroll
        for (int q = 0; q < 8; q++) {
            int ch = tid * 8 + q;
            int r = ch >> 4, c2 = (ch & 15) * 2;
            int gm = row0 + r, gk = kt + c2;
            int bytes = 0;
            if (gm < M) {
                int rem = (K - gk) * 4;
                bytes = rem >= 8 ? 8 : (rem > 0 ? rem : 0);
            }
            unsigned ds = sA_base + (unsigned)((buf * SA_ELEMS + r * SA_STRIDE + c2) * 4);
            const float* srcp = A + (long)gm * K + gk;
            CP8(ds, srcp, bytes);
        }
        // B: 1024 16B-chunks; thread gets 4
        #pragma unroll
        for (int q = 0; q < 4; q++) {
            int ch = tid * 4 + q;
            int r = ch >> 5, c4 = (ch & 31) * 4;
            unsigned ds = sB_base + (unsigned)((buf * SB_ELEMS + r * SB_STRIDE + c4) * 4);
            const float* srcp = Bm + (kt + r) * 128 + c4;
            CP16(ds, srcp);
        }
    };

    issue(0, 0);
    CP_COMMIT();

    for (int t = 0; t < T; t++) {
        int buf = t & 1;
        if (t + 1 < T) {
            issue(t + 1, (t + 1) & 1);
            CP_COMMIT();
            CP_WAIT(1);
        } else {
            CP_WAIT(0);
        }
        __syncthreads();

        const float* cA = sA + buf * SA_ELEMS;
        const float* cB = sB + buf * SB_ELEMS;
        #pragma unroll
        for (int ks = 0; ks < 4; ks++) {
            int c0 = ks * 8 + tq;
            unsigned int af[4][4];
            #pragma unroll
            for (int mi = 0; mi < 4; mi++) {
                int r = wm * 64 + mi * 16 + gq;
                af[mi][0] = __float_as_uint(to_tf32(cA[r * SA_STRIDE + c0]));
                af[mi][1] = __float_as_uint(to_tf32(cA[(r + 8) * SA_STRIDE + c0]));
                af[mi][2] = __float_as_uint(to_tf32(cA[r * SA_STRIDE + c0 + 4]));
                af[mi][3] = __float_as_uint(to_tf32(cA[(r + 8) * SA_STRIDE + c0 + 4]));
            }
            unsigned int bf[4][2];
            #pragma unroll
            for (int nb = 0; nb < 4; nb++) {
                int n = wn * 32 + nb * 8 + gq;
                bf[nb][0] = __float_as_uint(cB[(ks * 8 + tq) * SB_STRIDE + n]);
                bf[nb][1] = __float_as_uint(cB[(ks * 8 + 4 + tq) * SB_STRIDE + n]);
            }
            #pragma unroll
            for (int mi = 0; mi < 4; mi++)
                #pragma unroll
                for (int nb = 0; nb < 4; nb++)
                    MMA_TF32(acc[mi][nb], af[mi][0], af[mi][1], af[mi][2], af[mi][3],
                             bf[nb][0], bf[nb][1]);
        }
        __syncthreads();
    }

    // epilogue: fp16 store + fused alpha partial reduction
    int head = wn >> 1;
    #pragma unroll
    for (int mi = 0; mi < 4; mi++) {
        int rb = row0 + wm * 64 + mi * 16 + gq;
        float s_lo = 0.f, s_hi = 0.f, d_lo = 0.f, d_hi = 0.f;
        #pragma unroll
        for (int nb = 0; nb < 4; nb++) {
            int cc = wn * 32 + nb * 8 + tq * 2;
            float as0 = aS[cc], as1 = aS[cc + 1];
            float ad0 = aD[cc], ad1 = aD[cc + 1];
            s_lo += acc[mi][nb][0] * as0 + acc[mi][nb][1] * as1;
            d_lo += acc[mi][nb][0] * ad0 + acc[mi][nb][1] * ad1;
            s_hi += acc[mi][nb][2] * as0 + acc[mi][nb][3] * as1;
            d_hi += acc[mi][nb][2] * ad0 + acc[mi][nb][3] * ad1;
            if (rb < M)
                *reinterpret_cast<__half2*>(&Ch[(long)rb * 128 + cc]) =
                    __floats2half2_rn(acc[mi][nb][0], acc[mi][nb][1]);
            if (rb + 8 < M)
                *reinterpret_cast<__half2*>(&Ch[(long)(rb + 8) * 128 + cc]) =
                    __floats2half2_rn(acc[mi][nb][2], acc[mi][nb][3]);
        }
        if (rb < M) {
            atomicAdd(&g_asrc[2 * rb + head], s_lo);
            atomicAdd(&g_adst[2 * rb + head], d_lo);
        }
        if (rb + 8 < M) {
            atomicAdd(&g_asrc[2 * (rb + 8) + head], s_hi);
            atomicAdd(&g_adst[2 * (rb + 8) + head], d_hi);
        }
    }
}

// ---------------- GAT aggregation: warp per dst node, cached logits ----------------
__global__ void aggregate_kernel(const __half* __restrict__ xh,
                                 const float* __restrict__ bias,
                                 float* __restrict__ out) {
    int gw = (blockIdx.x * blockDim.x + threadIdx.x) >> 5;
    int lane = threadIdx.x & 31;
    if (gw >= NN) return;
    int i = gw;
    float ad0 = g_adst[2 * i], ad1 = g_adst[2 * i + 1];
    float es0 = lrelu(g_asrc[2 * i] + ad0);
    float es1 = lrelu(g_asrc[2 * i + 1] + ad1);
    int r0 = g_rowptr[i], r1 = g_rowptr[i + 1];

    const float NEG = -1e30f;
    int sc[4]; float e0c[4], e1c[4];
    float m0 = es0, m1 = es1;

    // pass 1: compute logits for first 4 strips (cached) + max
    #pragma unroll
    for (int q = 0; q < 4; q++) {
        int j = r0 + q * 32 + lane;
        if (j < r1) {
            int s = g_csrsrc[j];
            float e0 = lrelu(g_asrc[2 * s] + ad0);
            float e1 = lrelu(g_asrc[2 * s + 1] + ad1);
            sc[q] = s; e0c[q] = e0; e1c[q] = e1;
            m0 = fmaxf(m0, e0); m1 = fmaxf(m1, e1);
        } else { sc[q] = 0; e0c[q] = NEG; e1c[q] = NEG; }
    }
    for (int j = r0 + 128 + lane; j < r1; j += 32) {
        int s = g_csrsrc[j];
        m0 = fmaxf(m0, lrelu(g_asrc[2 * s] + ad0));
        m1 = fmaxf(m1, lrelu(g_asrc[2 * s + 1] + ad1));
    }
    #pragma unroll
    for (int o = 16; o; o >>= 1) {
        m0 = fmaxf(m0, __shfl_xor_sync(0xffffffffu, m0, o));
        m1 = fmaxf(m1, __shfl_xor_sync(0xffffffffu, m1, o));
    }

    // pass 2: denominator
    float s0 = 0.f, s1 = 0.f;
    #pragma unroll
    for (int q = 0; q < 4; q++) {
        s0 += __expf(e0c[q] - m0);
        s1 += __expf(e1c[q] - m1);
    }
    for (int j = r0 + 128 + lane; j < r1; j += 32) {
        int s = g_csrsrc[j];
        s0 += __expf(lrelu(g_asrc[2 * s] + ad0) - m0);
        s1 += __expf(lrelu(g_asrc[2 * s + 1] + ad1) - m1);
    }
    #pragma unroll
    for (int o = 16; o; o >>= 1) {
        s0 += __shfl_xor_sync(0xffffffffu, s0, o);
        s1 += __shfl_xor_sync(0xffffffffu, s1, o);
    }
    s0 += __expf(es0 - m0);
    s1 += __expf(es1 - m1);
    float inv0 = 1.f / (s0 + 1e-16f);
    float inv1 = 1.f / (s1 + 1e-16f);

    // pass 3: weighted message sum; lane covers cols [4*lane, 4*lane+4)
    int head = lane >> 4;
    float4 acc = make_float4(0.f, 0.f, 0.f, 0.f);
    // cached strips: pack (w0, w1) as half2, single shuffle per edge
    #pragma unroll
    for (int q = 0; q < 4; q++) {
        if (r0 + q * 32 >= r1) break;
        int s = sc[q];
        __half2 wh2 = __floats2half2_rn(__expf(e0c[q] - m0) * inv0,
                                        __expf(e1c[q] - m1) * inv1);
        unsigned wpu = *reinterpret_cast<unsigned*>(&wh2);
        int cnt = min(32, r1 - (r0 + q * 32));
        for (int k = 0; k < cnt; k++) {
            int      sk = __shfl_sync(0xffffffffu, s, k);
            unsigned wk = __shfl_sync(0xffffffffu, wpu, k);
            __half2 wv = *reinterpret_cast<__half2*>(&wk);
            float w = head ? __high2float(wv) : __low2float(wv);
            uint2 raw = *reinterpret_cast<const uint2*>(&xh[(long)sk * HD + lane * 4]);
            __half2 p0 = *reinterpret_cast<__half2*>(&raw.x);
            __half2 p1 = *reinterpret_cast<__half2*>(&raw.y);
            float2 f0 = __half22float2(p0);
            float2 f1 = __half22float2(p1);
            acc.x = fmaf(w, f0.x, acc.x);
            acc.y = fmaf(w, f0.y, acc.y);
            acc.z = fmaf(w, f1.x, acc.z);
            acc.w = fmaf(w, f1.y, acc.w);
        }
    }
    // remainder strips (recompute logits)
    for (int jb = r0 + 128; jb < r1; jb += 32) {
        int j = jb + lane;
        int s = 0; unsigned wpu = 0;
        if (j < r1) {
            s = g_csrsrc[j];
            __half2 wh2 = __floats2half2_rn(
                __expf(lrelu(g_asrc[2 * s] + ad0) - m0) * inv0,
                __expf(lrelu(g_asrc[2 * s + 1] + ad1) - m1) * inv1);
            wpu = *reinterpret_cast<unsigned*>(&wh2);
        }
        int cnt = min(32, r1 - jb);
        for (int k = 0; k < cnt; k++) {
            int      sk = __shfl_sync(0xffffffffu, s, k);
            unsigned wk = __shfl_sync(0xffffffffu, wpu, k);
            __half2 wv = *reinterpret_cast<__half2*>(&wk);
            float w = head ? __high2float(wv) : __low2float(wv);
            uint2 raw = *reinterpret_cast<const uint2*>(&xh[(long)sk * HD + lane * 4]);
            __half2 p0 = *reinterpret_cast<__half2*>(&raw.x);
            __half2 p1 = *reinterpret_cast<__half2*>(&raw.y);
            float2 f0 = __half22float2(p0);
            float2 f1 = __half22float2(p1);
            acc.x = fmaf(w, f0.x, acc.x);
            acc.y = fmaf(w, f0.y, acc.y);
            acc.z = fmaf(w, f1.x, acc.z);
            acc.w = fmaf(w, f1.y, acc.w);
        }
    }
    // self loop
    float wself = head ? (__expf(es1 - m1) * inv1) : (__expf(es0 - m0) * inv0);
    {
        uint2 raw = *reinterpret_cast<const uint2*>(&xh[(long)i * HD + lane * 4]);
        __half2 p0 = *reinterpret_cast<__half2*>(&raw.x);
        __half2 p1 = *reinterpret_cast<__half2*>(&raw.y);
        float2 f0 = __half22float2(p0);
        float2 f1 = __half22float2(p1);
        acc.x = fmaf(wself, f0.x, acc.x);
        acc.y = fmaf(wself, f0.y, acc.y);
        acc.z = fmaf(wself, f1.x, acc.z);
        acc.w = fmaf(wself, f1.y, acc.w);
    }

    float4 b = *reinterpret_cast<const float4*>(&bias[lane * 4]);
    float4 o;
    o.x = fmaxf(acc.x + b.x, 0.f);
    o.y = fmaxf(acc.y + b.y, 0.f);
    o.z = fmaxf(acc.z + b.z, 0.f);
    o.w = fmaxf(acc.w + b.w, 0.f);
    *reinterpret_cast<float4*>(&out[i * HD + lane * 4]) = o;
}

// ---------------- mean pool (parallel over 4 node-partitions) ----------------
__global__ void pool_kernel(const float* __restrict__ h) {
    int b = blockIdx.x;
    int t = threadIdx.x & 127, part = threadIdx.x >> 7;   // 512 threads
    __shared__ float ps[4][128];
    int r0 = g_root[b], r1 = g_root[b + 1];
    float s = 0.f;
    for (int n = r0 + part; n < r1; n += 4) s += h[n * 128 + t];
    ps[part][t] = s;
    __syncthreads();
    if (part == 0)
        g_pooled[b * 128 + t] = (ps[0][t] + ps[1][t] + ps[2][t] + ps[3][t]) / (float)(r1 - r0);
}

// ---------------- readout + news + concat + sigmoid ----------------
__global__ void head_kernel(const float* __restrict__ x,
                            const float* __restrict__ Wr, const float* __restrict__ br,
                            const float* __restrict__ Wn, const float* __restrict__ bn,
                            const float* __restrict__ Wc, const float* __restrict__ bc,
                            float* __restrict__ out) {
    int b = blockIdx.x;
    int t = threadIdx.x;   // 128
    __shared__ float pooled[128];
    __shared__ float xroot[312];
    __shared__ float red[128];

    int r0 = g_root[b];
    pooled[t] = g_pooled[b * 128 + t];
    for (int k = t; k < IN_DIM; k += 128) xroot[k] = x[(long)r0 * IN_DIM + k];
    __syncthreads();

    float accg = br[t];
    #pragma unroll 4
    for (int k = 0; k < 128; k++) accg = fmaf(pooled[k], Wr[k * 128 + t], accg);
    float g = fmaxf(accg, 0.f);

    float accn = bn[t];
    for (int k = 0; k < IN_DIM; k++) accn = fmaf(xroot[k], Wn[k * 128 + t], accn);
    float nws = fmaxf(accn, 0.f);

    red[t] = g * Wc[t] + nws * Wc[128 + t];
    __syncthreads();
    for (int o = 64; o; o >>= 1) {
        if (t < o) red[t] += red[t + o];
        __syncthreads();
    }
    if (t == 0) out[b] = 1.f / (1.f + expf(-(red[0] + bc[0])));
}

// ---------------- launch ----------------
extern "C" void kernel_launch(void* const* d_in, const int* in_sizes, int n_in,
                              void* d_out, int out_size) {
    const float* x   = (const float*)d_in[0];
    const float* W0  = (const float*)d_in[1];
    const float* as0 = (const float*)d_in[2];
    const float* ad0 = (const float*)d_in[3];
    const float* b0  = (const float*)d_in[4];
    const float* W1  = (const float*)d_in[5];
    const float* as1 = (const float*)d_in[6];
    const float* ad1 = (const float*)d_in[7];
    const float* b1  = (const float*)d_in[8];
    const float* Wn  = (const float*)d_in[9];
    const float* bn  = (const float*)d_in[10];
    const float* Wr  = (const float*)d_in[11];
    const float* br  = (const float*)d_in[12];
    const float* Wc  = (const float*)d_in[13];
    const float* bc  = (const float*)d_in[14];
    const int*   ei  = (const int*)d_in[15];
    const int*   batch = (const int*)d_in[16];
    float* out = (float*)d_out;

    const int* src = ei;
    const int* dst = ei + EE;

    void *p_xwh, *p_h, *p_b0, *p_b1;
    cudaGetSymbolAddress(&p_xwh, g_xwh);
    cudaGetSymbolAddress(&p_h, g_h);
    cudaGetSymbolAddress(&p_b0, g_B0);
    cudaGetSymbolAddress(&p_b1, g_B1);
    __half* xwh = (__half*)p_xwh;
    float* hbuf = (float*)p_h;

    // one-time setup: side stream, fork/join events, gemm smem opt-in
    static cudaStream_t s1 = nullptr;
    static cudaEvent_t evFork = nullptr, evJoin = nullptr;
    if (s1 == nullptr) {
        cudaStreamCreateWithFlags(&s1, cudaStreamNonBlocking);
        cudaEventCreateWithFlags(&evFork, cudaEventDisableTiming);
        cudaEventCreateWithFlags(&evJoin, cudaEventDisableTiming);
        cudaFuncSetAttribute(gemm_tf32, cudaFuncAttributeMaxDynamicSharedMemorySize,
                             GEMM_SMEM_BYTES);
    }

    // fork: CSR build on s1 runs concurrently with weight prep + GEMM0 on s0
    cudaEventRecord(evFork, 0);
    cudaStreamWaitEvent(s1, evFork, 0);

    zero_csr_kernel<<<(NN + 255) / 256, 256, 0, s1>>>();
    count_kernel<<<(EE / 4 + 255) / 256, 256, 0, s1>>>(dst);
    scan_kernel<<<1, 1024, 0, s1>>>();
    fill_kernel<<<(EE / 4 + 255) / 256, 256, 0, s1>>>(src, dst);
    roots_kernel<<<1, 256, 0, s1>>>(batch);
    cudaEventRecord(evJoin, s1);

    // s0: weight prep + GEMM0 (fused alpha)
    convB_kernel<<<(KP0 * 128 + 255) / 256, 256>>>(W0, (float*)p_b0, IN_DIM, KP0);
    convB_kernel<<<(128 * 128 + 255) / 256, 256>>>(W1, (float*)p_b1, 128, 128);
    zero_alpha_kernel<<<(NN * NH + 255) / 256, 256>>>();
    gemm_tf32<<<(NN + 127) / 128, 256, GEMM_SMEM_BYTES>>>(
        x, (float*)p_b0, xwh, as0, ad0, NN, IN_DIM, KP0);

    // join: aggregation needs both CSR and GEMM0
    cudaStreamWaitEvent(0, evJoin, 0);

    aggregate_kernel<<<(NN + 7) / 8, 256>>>(xwh, b0, hbuf);

    // GAT layer 1
    zero_alpha_kernel<<<(NN * NH + 255) / 256, 256>>>();
    gemm_tf32<<<(NN + 127) / 128, 256, GEMM_SMEM_BYTES>>>(
        hbuf, (float*)p_b1, xwh, as1, ad1, NN, 128, 128);
    aggregate_kernel<<<(NN + 7) / 8, 256>>>(xwh, b1, hbuf);

    // pooling + readout + news + concat + sigmoid
    pool_kernel<<<BB, 512>>>(hbuf);
    head_kernel<<<BB, 128>>>(x, Wr, br, Wn, bn, Wc, bc, out);
}

// round 8
// speedup vs baseline: 2.1981x; 1.0946x over previous
#include <cuda_runtime.h>
#include <cuda_fp16.h>
#include <stdint.h>
#include <math.h>

// Problem constants (fixed shapes for this dataset)
#define NN 50000
#define EE 800000
#define BB 128
#define IN_DIM 310
#define KP0 320      // IN_DIM padded to multiple of 32
#define HD 128       // 2 heads x 64
#define NH 2

// ---------------- scratch (static device globals; no allocation) ----------------
__device__ __align__(16) __half g_xwh[NN * HD];      // GEMM output fp16 (for gather)
__device__ __align__(16) float g_h[NN * HD];         // aggregated layer output
__device__ __align__(8) float g_asrc[NN * NH];
__device__ __align__(8) float g_adst[NN * NH];
__device__ int   g_deg[NN];
__device__ int   g_cursor[NN];
__device__ int   g_rowptr[NN + 1];
__device__ int   g_csrsrc[EE];
__device__ int   g_root[BB + 1];
__device__ __align__(16) float g_pooled[BB * 128];
// tf32-rounded weight matrices, zero-padded along K
__device__ __align__(16) float g_B0[KP0 * 128];
__device__ __align__(16) float g_B1[128 * 128];

__device__ __forceinline__ float lrelu(float z) { return z > 0.f ? z : 0.2f * z; }
__device__ __forceinline__ float to_tf32(float x) {
    float r;
    asm("cvt.rna.tf32.f32 %0, %1;" : "=f"(r) : "f"(x));
    return r;
}

// ---------------- CSR build ----------------
__global__ void zero_csr_kernel() {
    int i = blockIdx.x * blockDim.x + threadIdx.x;
    if (i < NN) { g_deg[i] = 0; g_cursor[i] = 0; }
}

__global__ void count_kernel(const int* __restrict__ dst) {
    int i = blockIdx.x * blockDim.x + threadIdx.x;
    if (i < EE / 4) {
        int4 d = reinterpret_cast<const int4*>(dst)[i];
        atomicAdd(&g_deg[d.x], 1);
        atomicAdd(&g_deg[d.y], 1);
        atomicAdd(&g_deg[d.z], 1);
        atomicAdd(&g_deg[d.w], 1);
    }
}

// chunked scan: 1024 threads, each owns a contiguous chunk
__global__ void scan_kernel() {
    const int CH = (NN + 1023) / 1024;     // 49
    __shared__ int ws[32];
    int t = threadIdx.x, lane = t & 31, wid = t >> 5;
    int lo = t * CH, hi = min(lo + CH, NN);
    if (lo > NN) lo = NN;
    if (hi < lo) hi = lo;
    int sum = 0;
    for (int i = lo; i < hi; i++) sum += g_deg[i];
    int x = sum;
    #pragma unroll
    for (int o = 1; o < 32; o <<= 1) {
        int y = __shfl_up_sync(0xffffffffu, x, o);
        if (lane >= o) x += y;
    }
    if (lane == 31) ws[wid] = x;
    __syncthreads();
    if (wid == 0) {
        int w = ws[lane];
        #pragma unroll
        for (int o = 1; o < 32; o <<= 1) {
            int y = __shfl_up_sync(0xffffffffu, w, o);
            if (lane >= o) w += y;
        }
        ws[lane] = w;
    }
    __syncthreads();
    int run = x - sum + (wid ? ws[wid - 1] : 0);
    for (int i = lo; i < hi; i++) { g_rowptr[i] = run; run += g_deg[i]; }
    if (t == 1023) g_rowptr[NN] = run;
}

__global__ void fill_kernel(const int* __restrict__ src, const int* __restrict__ dst) {
    int i = blockIdx.x * blockDim.x + threadIdx.x;
    if (i < EE / 4) {
        int4 s4 = reinterpret_cast<const int4*>(src)[i];
        int4 d4 = reinterpret_cast<const int4*>(dst)[i];
        int p0 = g_rowptr[d4.x] + atomicAdd(&g_cursor[d4.x], 1);
        int p1 = g_rowptr[d4.y] + atomicAdd(&g_cursor[d4.y], 1);
        int p2 = g_rowptr[d4.z] + atomicAdd(&g_cursor[d4.z], 1);
        int p3 = g_rowptr[d4.w] + atomicAdd(&g_cursor[d4.w], 1);
        g_csrsrc[p0] = s4.x;
        g_csrsrc[p1] = s4.y;
        g_csrsrc[p2] = s4.z;
        g_csrsrc[p3] = s4.w;
    }
}

__global__ void roots_kernel(const int* __restrict__ batch) {
    int b = threadIdx.x;
    if (b > BB) return;
    if (b == BB) { g_root[BB] = NN; return; }
    int lo = 0, hi = NN;
    while (lo < hi) {
        int mid = (lo + hi) >> 1;
        if (batch[mid] < b) lo = mid + 1; else hi = mid;
    }
    g_root[b] = lo;
}

// ---------------- weight prep: fp32 -> tf32-rounded fp32, zero-padded ----------------
__global__ void convB_kernel(const float* __restrict__ W, float* __restrict__ outB,
                             int K, int Kp) {
    int i = blockIdx.x * blockDim.x + threadIdx.x;
    if (i >= Kp * 128) return;
    int k = i >> 7;
    float v = (k < K) ? W[i] : 0.f;
    outB[i] = to_tf32(v);
}

// ---------------- tf32 tensor-core GEMM, cp.async double-buffered, fused alpha ----
#define MMA_TF32(Cr, a0, a1, a2, a3, b0, b1) \
    asm volatile("mma.sync.aligned.m16n8k8.row.col.f32.tf32.tf32.f32 " \
        "{%0,%1,%2,%3},{%4,%5,%6,%7},{%8,%9},{%0,%1,%2,%3};" \
        : "+f"((Cr)[0]), "+f"((Cr)[1]), "+f"((Cr)[2]), "+f"((Cr)[3]) \
        : "r"(a0), "r"(a1), "r"(a2), "r"(a3), "r"(b0), "r"(b1))
// A path: 8-byte cp.async (src only guaranteed 8B-aligned: row stride K*4 = 1240B)
#define CP8(dst, src, bytes) \
    asm volatile("cp.async.ca.shared.global [%0], [%1], 8, %2;" \
        :: "r"(dst), "l"(src), "r"(bytes))
// B path: 16-byte cp.async (row stride 512B, always 16B-aligned)
#define CP16(dst, src) \
    asm volatile("cp.async.cg.shared.global [%0], [%1], 16;" \
        :: "r"(dst), "l"(src))
#define CP_COMMIT() asm volatile("cp.async.commit_group;")
#define CP_WAIT(n)  asm volatile("cp.async.wait_group %0;" :: "n"(n))

#define SA_STRIDE 36
#define SB_STRIDE 136
#define SA_ELEMS (128 * SA_STRIDE)
#define SB_ELEMS (32 * SB_STRIDE)
#define GEMM_SMEM_BYTES ((2 * SA_ELEMS + 2 * SB_ELEMS) * 4)

__global__ __launch_bounds__(256) void gemm_tf32(
    const float* __restrict__ A, const float* __restrict__ Bm,
    __half* __restrict__ Ch,
    const float* __restrict__ aS, const float* __restrict__ aD,
    int M, int K, int Kp)
{
    extern __shared__ float smem[];
    float* sA = smem;                       // [2][128][36]
    float* sB = smem + 2 * SA_ELEMS;        // [2][32][136]
    __shared__ float2 salS[128][4];         // per-(row, wn) alpha_src partials
    __shared__ float2 salD[128][4];         // (x = asrc partial, y = adst partial)

    int tid = threadIdx.x;
    int lane = tid & 31, warp = tid >> 5;
    int wm = warp >> 2, wn = warp & 3;   // 2 x 4 warps; warp tile 64 x 32
    int row0 = blockIdx.x * 128;
    int gq = lane >> 2, tq = lane & 3;

    float acc[4][4][4];
    #pragma unroll
    for (int a = 0; a < 4; a++)
        #pragma unroll
        for (int b = 0; b < 4; b++)
            #pragma unroll
            for (int c = 0; c < 4; c++) acc[a][b][c] = 0.f;

    unsigned sA_base = (unsigned)__cvta_generic_to_shared(sA);
    unsigned sB_base = (unsigned)__cvta_generic_to_shared(sB);
    int T = Kp / 32;

    // async tile loader: A via 8B chunks (alignment-safe), B via 16B chunks
    auto issue = [&](int t, int buf) {
        int kt = t * 32;
        #pragma unroll
        for (int q = 0; q < 8; q++) {
            int ch = tid * 8 + q;
            int r = ch >> 4, c2 = (ch & 15) * 2;
            int gm = row0 + r, gk = kt + c2;
            int bytes = 0;
            if (gm < M) {
                int rem = (K - gk) * 4;
                bytes = rem >= 8 ? 8 : (rem > 0 ? rem : 0);
            }
            unsigned ds = sA_base + (unsigned)((buf * SA_ELEMS + r * SA_STRIDE + c2) * 4);
            const float* srcp = A + (long)gm * K + gk;
            CP8(ds, srcp, bytes);
        }
        #pragma unroll
        for (int q = 0; q < 4; q++) {
            int ch = tid * 4 + q;
            int r = ch >> 5, c4 = (ch & 31) * 4;
            unsigned ds = sB_base + (unsigned)((buf * SB_ELEMS + r * SB_STRIDE + c4) * 4);
            const float* srcp = Bm + (kt + r) * 128 + c4;
            CP16(ds, srcp);
        }
    };

    issue(0, 0);
    CP_COMMIT();

    for (int t = 0; t < T; t++) {
        int buf = t & 1;
        if (t + 1 < T) {
            issue(t + 1, (t + 1) & 1);
            CP_COMMIT();
            CP_WAIT(1);
        } else {
            CP_WAIT(0);
        }
        __syncthreads();

        const float* cA = sA + buf * SA_ELEMS;
        const float* cB = sB + buf * SB_ELEMS;
        #pragma unroll
        for (int ks = 0; ks < 4; ks++) {
            int c0 = ks * 8 + tq;
            unsigned int af[4][4];
            #pragma unroll
            for (int mi = 0; mi < 4; mi++) {
                int r = wm * 64 + mi * 16 + gq;
                af[mi][0] = __float_as_uint(to_tf32(cA[r * SA_STRIDE + c0]));
                af[mi][1] = __float_as_uint(to_tf32(cA[(r + 8) * SA_STRIDE + c0]));
                af[mi][2] = __float_as_uint(to_tf32(cA[r * SA_STRIDE + c0 + 4]));
                af[mi][3] = __float_as_uint(to_tf32(cA[(r + 8) * SA_STRIDE + c0 + 4]));
            }
            unsigned int bf[4][2];
            #pragma unroll
            for (int nb = 0; nb < 4; nb++) {
                int n = wn * 32 + nb * 8 + gq;
                bf[nb][0] = __float_as_uint(cB[(ks * 8 + tq) * SB_STRIDE + n]);
                bf[nb][1] = __float_as_uint(cB[(ks * 8 + 4 + tq) * SB_STRIDE + n]);
            }
            #pragma unroll
            for (int mi = 0; mi < 4; mi++)
                #pragma unroll
                for (int nb = 0; nb < 4; nb++)
                    MMA_TF32(acc[mi][nb], af[mi][0], af[mi][1], af[mi][2], af[mi][3],
                             bf[nb][0], bf[nb][1]);
        }
        __syncthreads();
    }

    // epilogue: fp16 store + alpha partials (shfl-reduced over tq, smem-combined)
    #pragma unroll
    for (int mi = 0; mi < 4; mi++) {
        int rb = row0 + wm * 64 + mi * 16 + gq;
        float s_lo = 0.f, s_hi = 0.f, d_lo = 0.f, d_hi = 0.f;
        #pragma unroll
        for (int nb = 0; nb < 4; nb++) {
            int cc = wn * 32 + nb * 8 + tq * 2;
            float as0 = aS[cc], as1 = aS[cc + 1];
            float ad0 = aD[cc], ad1 = aD[cc + 1];
            s_lo += acc[mi][nb][0] * as0 + acc[mi][nb][1] * as1;
            d_lo += acc[mi][nb][0] * ad0 + acc[mi][nb][1] * ad1;
            s_hi += acc[mi][nb][2] * as0 + acc[mi][nb][3] * as1;
            d_hi += acc[mi][nb][2] * ad0 + acc[mi][nb][3] * ad1;
            if (rb < M)
                *reinterpret_cast<__half2*>(&Ch[(long)rb * 128 + cc]) =
                    __floats2half2_rn(acc[mi][nb][0], acc[mi][nb][1]);
            if (rb + 8 < M)
                *reinterpret_cast<__half2*>(&Ch[(long)(rb + 8) * 128 + cc]) =
                    __floats2half2_rn(acc[mi][nb][2], acc[mi][nb][3]);
        }
        // reduce over the 4 tq lanes of this group
        #pragma unroll
        for (int o = 1; o < 4; o <<= 1) {
            s_lo += __shfl_down_sync(0xffffffffu, s_lo, o, 4);
            d_lo += __shfl_down_sync(0xffffffffu, d_lo, o, 4);
            s_hi += __shfl_down_sync(0xffffffffu, s_hi, o, 4);
            d_hi += __shfl_down_sync(0xffffffffu, d_hi, o, 4);
        }
        if (tq == 0) {
            int rl = wm * 64 + mi * 16 + gq;
            salS[rl][wn] = make_float2(s_lo, d_lo);
            salD[rl + 8][wn] = salD[rl + 8][wn];  // placeholder (avoid unused warn)
            salS[rl + 8][wn] = make_float2(s_hi, d_hi);
        }
    }
    __syncthreads();
    // final combine: thread t -> (row = t>>1, head = t&1); head h sums wn {2h, 2h+1}
    {
        int row = tid >> 1, head = tid & 1;
        float2 a = salS[row][2 * head];
        float2 b = salS[row][2 * head + 1];
        int gr = row0 + row;
        if (gr < M) {
            g_asrc[2 * gr + head] = a.x + b.x;
            g_adst[2 * gr + head] = a.y + b.y;
        }
    }
}

// ---------------- GAT aggregation: warp per dst node, SINGLE PASS ----------------
// softmax shift-invariance: skip segment-max; fuse denominator into message sweep.
__global__ void aggregate_kernel(const __half* __restrict__ xh,
                                 const float* __restrict__ bias,
                                 float* __restrict__ out) {
    int gw = (blockIdx.x * blockDim.x + threadIdx.x) >> 5;
    int lane = threadIdx.x & 31;
    if (gw >= NN) return;
    int i = gw;
    int head = lane >> 4;
    float2 adp = *reinterpret_cast<const float2*>(&g_adst[2 * i]);
    float2 asp = *reinterpret_cast<const float2*>(&g_asrc[2 * i]);
    float ad0 = adp.x, ad1 = adp.y;
    float eSelf = head ? lrelu(asp.y + ad1) : lrelu(asp.x + ad0);
    int r0 = g_rowptr[i], r1 = g_rowptr[i + 1];

    // self-loop seeds the accumulators
    float wself = __expf(eSelf);
    float den = wself;
    float4 acc;
    {
        uint2 raw = *reinterpret_cast<const uint2*>(&xh[(long)i * HD + lane * 4]);
        __half2 p0 = *reinterpret_cast<__half2*>(&raw.x);
        __half2 p1 = *reinterpret_cast<__half2*>(&raw.y);
        float2 f0 = __half22float2(p0);
        float2 f1 = __half22float2(p1);
        acc = make_float4(wself * f0.x, wself * f0.y, wself * f1.x, wself * f1.y);
    }

    // single sweep: lane j owns edge j's logits; broadcast (s, e-pair); every
    // lane exps its own head's logit and accumulates den + weighted message.
    for (int jb = r0; jb < r1; jb += 32) {
        int j = jb + lane;
        int s = 0; unsigned epk = 0;
        if (j < r1) {
            s = g_csrsrc[j];
            float2 a = *reinterpret_cast<const float2*>(&g_asrc[2 * s]);
            __half2 eh = __floats2half2_rn(lrelu(a.x + ad0), lrelu(a.y + ad1));
            epk = *reinterpret_cast<unsigned*>(&eh);
        }
        int cnt = min(32, r1 - jb);
        for (int k = 0; k < cnt; k++) {
            int      sk = __shfl_sync(0xffffffffu, s, k);
            unsigned ek = __shfl_sync(0xffffffffu, epk, k);
            __half2 ev = *reinterpret_cast<__half2*>(&ek);
            float e = head ? __high2float(ev) : __low2float(ev);
            float w = __expf(e);
            den += w;
            uint2 raw = *reinterpret_cast<const uint2*>(&xh[(long)sk * HD + lane * 4]);
            __half2 p0 = *reinterpret_cast<__half2*>(&raw.x);
            __half2 p1 = *reinterpret_cast<__half2*>(&raw.y);
            float2 f0 = __half22float2(p0);
            float2 f1 = __half22float2(p1);
            acc.x = fmaf(w, f0.x, acc.x);
            acc.y = fmaf(w, f0.y, acc.y);
            acc.z = fmaf(w, f1.x, acc.z);
            acc.w = fmaf(w, f1.y, acc.w);
        }
    }

    float inv = 1.f / (den + 1e-16f);
    float4 b = *reinterpret_cast<const float4*>(&bias[lane * 4]);
    float4 o;
    o.x = fmaxf(fmaf(acc.x, inv, b.x), 0.f);
    o.y = fmaxf(fmaf(acc.y, inv, b.y), 0.f);
    o.z = fmaxf(fmaf(acc.z, inv, b.z), 0.f);
    o.w = fmaxf(fmaf(acc.w, inv, b.w), 0.f);
    *reinterpret_cast<float4*>(&out[i * HD + lane * 4]) = o;
}

// ---------------- mean pool (parallel over 4 node-partitions) ----------------
__global__ void pool_kernel(const float* __restrict__ h) {
    int b = blockIdx.x;
    int t = threadIdx.x & 127, part = threadIdx.x >> 7;   // 512 threads
    __shared__ float ps[4][128];
    int r0 = g_root[b], r1 = g_root[b + 1];
    float s = 0.f;
    for (int n = r0 + part; n < r1; n += 4) s += h[n * 128 + t];
    ps[part][t] = s;
    __syncthreads();
    if (part == 0)
        g_pooled[b * 128 + t] = (ps[0][t] + ps[1][t] + ps[2][t] + ps[3][t]) / (float)(r1 - r0);
}

// ---------------- readout + news + concat + sigmoid ----------------
__global__ void head_kernel(const float* __restrict__ x,
                            const float* __restrict__ Wr, const float* __restrict__ br,
                            const float* __restrict__ Wn, const float* __restrict__ bn,
                            const float* __restrict__ Wc, const float* __restrict__ bc,
                            float* __restrict__ out) {
    int b = blockIdx.x;
    int t = threadIdx.x;   // 128
    __shared__ float pooled[128];
    __shared__ float xroot[312];
    __shared__ float red[128];

    int r0 = g_root[b];
    pooled[t] = g_pooled[b * 128 + t];
    for (int k = t; k < IN_DIM; k += 128) xroot[k] = x[(long)r0 * IN_DIM + k];
    __syncthreads();

    float accg = br[t];
    #pragma unroll 4
    for (int k = 0; k < 128; k++) accg = fmaf(pooled[k], Wr[k * 128 + t], accg);
    float g = fmaxf(accg, 0.f);

    float accn = bn[t];
    for (int k = 0; k < IN_DIM; k++) accn = fmaf(xroot[k], Wn[k * 128 + t], accn);
    float nws = fmaxf(accn, 0.f);

    red[t] = g * Wc[t] + nws * Wc[128 + t];
    __syncthreads();
    for (int o = 64; o; o >>= 1) {
        if (t < o) red[t] += red[t + o];
        __syncthreads();
    }
    if (t == 0) out[b] = 1.f / (1.f + expf(-(red[0] + bc[0])));
}

// ---------------- launch ----------------
extern "C" void kernel_launch(void* const* d_in, const int* in_sizes, int n_in,
                              void* d_out, int out_size) {
    const float* x   = (const float*)d_in[0];
    const float* W0  = (const float*)d_in[1];
    const float* as0 = (const float*)d_in[2];
    const float* ad0 = (const float*)d_in[3];
    const float* b0  = (const float*)d_in[4];
    const float* W1  = (const float*)d_in[5];
    const float* as1 = (const float*)d_in[6];
    const float* ad1 = (const float*)d_in[7];
    const float* b1  = (const float*)d_in[8];
    const float* Wn  = (const float*)d_in[9];
    const float* bn  = (const float*)d_in[10];
    const float* Wr  = (const float*)d_in[11];
    const float* br  = (const float*)d_in[12];
    const float* Wc  = (const float*)d_in[13];
    const float* bc  = (const float*)d_in[14];
    const int*   ei  = (const int*)d_in[15];
    const int*   batch = (const int*)d_in[16];
    float* out = (float*)d_out;

    const int* src = ei;
    const int* dst = ei + EE;

    void *p_xwh, *p_h, *p_b0, *p_b1;
    cudaGetSymbolAddress(&p_xwh, g_xwh);
    cudaGetSymbolAddress(&p_h, g_h);
    cudaGetSymbolAddress(&p_b0, g_B0);
    cudaGetSymbolAddress(&p_b1, g_B1);
    __half* xwh = (__half*)p_xwh;
    float* hbuf = (float*)p_h;

    // one-time setup: side stream, fork/join events, gemm smem opt-in
    static cudaStream_t s1 = nullptr;
    static cudaEvent_t evFork = nullptr, evJoin = nullptr;
    if (s1 == nullptr) {
        cudaStreamCreateWithFlags(&s1, cudaStreamNonBlocking);
        cudaEventCreateWithFlags(&evFork, cudaEventDisableTiming);
        cudaEventCreateWithFlags(&evJoin, cudaEventDisableTiming);
        cudaFuncSetAttribute(gemm_tf32, cudaFuncAttributeMaxDynamicSharedMemorySize,
                             GEMM_SMEM_BYTES);
    }

    // fork: CSR build on s1 runs concurrently with weight prep + GEMM0 on s0
    cudaEventRecord(evFork, 0);
    cudaStreamWaitEvent(s1, evFork, 0);

    zero_csr_kernel<<<(NN + 255) / 256, 256, 0, s1>>>();
    count_kernel<<<(EE / 4 + 255) / 256, 256, 0, s1>>>(dst);
    scan_kernel<<<1, 1024, 0, s1>>>();
    fill_kernel<<<(EE / 4 + 255) / 256, 256, 0, s1>>>(src, dst);
    roots_kernel<<<1, 256, 0, s1>>>(batch);
    cudaEventRecord(evJoin, s1);

    // s0: weight prep + GEMM0 (fused alpha, no zeroing needed)
    convB_kernel<<<(KP0 * 128 + 255) / 256, 256>>>(W0, (float*)p_b0, IN_DIM, KP0);
    convB_kernel<<<(128 * 128 + 255) / 256, 256>>>(W1, (float*)p_b1, 128, 128);
    gemm_tf32<<<(NN + 127) / 128, 256, GEMM_SMEM_BYTES>>>(
        x, (float*)p_b0, xwh, as0, ad0, NN, IN_DIM, KP0);

    // join: aggregation needs both CSR and GEMM0
    cudaStreamWaitEvent(0, evJoin, 0);

    aggregate_kernel<<<(NN + 7) / 8, 256>>>(xwh, b0, hbuf);

    // GAT layer 1
    gemm_tf32<<<(NN + 127) / 128, 256, GEMM_SMEM_BYTES>>>(
        hbuf, (float*)p_b1, xwh, as1, ad1, NN, 128, 128);
    aggregate_kernel<<<(NN + 7) / 8, 256>>>(xwh, b1, hbuf);

    // pooling + readout + news + concat + sigmoid
    pool_kernel<<<BB, 512>>>(hbuf);
    head_kernel<<<BB, 128>>>(x, Wr, br, Wn, bn, Wc, bc, out);
}